// round 12
// baseline (speedup 1.0000x reference)
#include <cuda_runtime.h>
#include <cuda_bf16.h>
#include <math.h>
#include <stdint.h>

// ---------------- problem constants ----------------
#define NN 10000
#define EE 60000
#define TT 2
#define NH 8
#define F0 2048
#define F1 1024
#define D1 128
#define F2 512
#define D2 64
#define OUTF 8

typedef __nv_bfloat16 bf16;
typedef __nv_bfloat162 bf162;

// ---------------- bf16 scratch offsets (elements) ----------------
#define OB_XB      ((size_t)0)                               // TT*NN*F0
#define OB_WKQV1   (OB_XB + (size_t)TT*NN*F0)                // TT*F0*3F1
#define OB_WA1     (OB_WKQV1 + (size_t)TT*F0*3*F1)
#define OB_AREL1   (OB_WA1 + (size_t)TT*F1*F1)
#define OB_MREL1   (OB_AREL1 + (size_t)4*NH*D1*D1)           // must follow AREL1
#define OB_WKQV2   (OB_MREL1 + (size_t)4*NH*D1*D1)
#define OB_WA2     (OB_WKQV2 + (size_t)TT*F1*3*F2)
#define OB_AREL2   (OB_WA2 + (size_t)TT*F2*F2)
#define OB_MREL2   (OB_AREL2 + (size_t)4*NH*D2*D2)           // must follow AREL2
#define OB_KQV1    (OB_MREL2 + (size_t)4*NH*D2*D2)           // TT*NN*3F1
#define OB_KR1     (OB_KQV1 + (size_t)TT*NN*3*F1)            // 4*NN*F1
#define OB_VR1     (OB_KR1 + (size_t)4*NN*F1)                // must follow KR1
#define OB_ACT1    (OB_VR1 + (size_t)4*NN*F1)                // TT*NN*F1
#define OB_H1      (OB_ACT1 + (size_t)TT*NN*F1)
#define OB_KQV2    (OB_H1 + (size_t)TT*NN*F1)                // TT*NN*3F2
#define OB_KR2     (OB_KQV2 + (size_t)TT*NN*3*F2)
#define OB_VR2     (OB_KR2 + (size_t)4*NN*F2)                // must follow KR2
#define OB_ACT2    (OB_VR2 + (size_t)4*NN*F2)
#define OB_H2      (OB_ACT2 + (size_t)TT*NN*F2)
#define OB_TOTAL   (OB_H2 + (size_t)TT*NN*F2)

__device__ bf16 g_bf[OB_TOTAL];

// ---------------- fp32 scratch ----------------
#define OF_OUTE   ((size_t)0)                                // 4*NN*F1
#define OF_SB     (OF_OUTE + (size_t)4*NN*F1)                // 4*NN*NH
#define OF_BKQV1  (OF_SB + (size_t)4*NN*NH)                  // TT*3F1
#define OF_BKQV2  (OF_BKQV1 + (size_t)TT*3*F1)               // TT*3F2
#define OF_TOTAL  (OF_BKQV2 + (size_t)TT*3*F2)

__device__ float g_f32[OF_TOTAL];

// ---------------- asm helpers ----------------
__device__ __forceinline__ uint32_t smem_u32(const void* p) {
    return (uint32_t)__cvta_generic_to_shared(p);
}
__device__ __forceinline__ void cp16(uint32_t dst, const void* src, int sz) {
    asm volatile("cp.async.cg.shared.global [%0], [%1], 16, %2;" :: "r"(dst), "l"(src), "r"(sz));
}
__device__ __forceinline__ void cp_commit() { asm volatile("cp.async.commit_group;"); }
template<int N> __device__ __forceinline__ void cp_wait() {
    asm volatile("cp.async.wait_group %0;" :: "n"(N));
}
__device__ __forceinline__ void ldsm4(uint32_t& r0, uint32_t& r1, uint32_t& r2, uint32_t& r3, uint32_t a) {
    asm volatile("ldmatrix.sync.aligned.m8n8.x4.shared.b16 {%0,%1,%2,%3}, [%4];"
                 : "=r"(r0), "=r"(r1), "=r"(r2), "=r"(r3) : "r"(a));
}
__device__ __forceinline__ void ldsm4t(uint32_t& r0, uint32_t& r1, uint32_t& r2, uint32_t& r3, uint32_t a) {
    asm volatile("ldmatrix.sync.aligned.m8n8.x4.trans.shared.b16 {%0,%1,%2,%3}, [%4];"
                 : "=r"(r0), "=r"(r1), "=r"(r2), "=r"(r3) : "r"(a));
}
__device__ __forceinline__ void mma_bf16(float* c, const uint32_t* a, const uint32_t* b) {
    asm volatile("mma.sync.aligned.m16n8k16.row.col.f32.bf16.bf16.f32 "
                 "{%0,%1,%2,%3}, {%4,%5,%6,%7}, {%8,%9}, {%0,%1,%2,%3};"
                 : "+f"(c[0]), "+f"(c[1]), "+f"(c[2]), "+f"(c[3])
                 : "r"(a[0]), "r"(a[1]), "r"(a[2]), "r"(a[3]), "r"(b[0]), "r"(b[1]));
}

// ---------------- conversion / pack kernels ----------------
__global__ void cvt_bf4(const float* __restrict__ in, bf16* __restrict__ out, size_t n4) {
    size_t stride = (size_t)gridDim.x * blockDim.x;
    for (size_t i = (size_t)blockIdx.x * blockDim.x + threadIdx.x; i < n4; i += stride) {
        float4 v = ((const float4*)in)[i];
        bf162 a, b;
        a.x = __float2bfloat16(v.x); a.y = __float2bfloat16(v.y);
        b.x = __float2bfloat16(v.z); b.y = __float2bfloat16(v.w);
        ((bf162*)out)[i * 2] = a;
        ((bf162*)out)[i * 2 + 1] = b;
    }
}

// pack 3 weight matrices [T,Kd,Fo] along N -> out [T,Kd,3*Fo] bf16
__global__ void pack3w(const float* __restrict__ Wk, const float* __restrict__ Wq,
                       const float* __restrict__ Wv, bf16* __restrict__ out, int Kd, int Fo) {
    size_t total4 = (size_t)TT * Kd * 3 * Fo / 4;
    size_t stride = (size_t)gridDim.x * blockDim.x;
    for (size_t i = (size_t)blockIdx.x * blockDim.x + threadIdx.x; i < total4; i += stride) {
        size_t idx = i * 4;
        int j = (int)(idx % (size_t)(3 * Fo));
        size_t tk = idx / (size_t)(3 * Fo);
        int m = j / Fo, c = j % Fo;
        const float* W = (m == 0) ? Wk : ((m == 1) ? Wq : Wv);
        float4 v = *(const float4*)(W + tk * Fo + c);
        bf162 a, b;
        a.x = __float2bfloat16(v.x); a.y = __float2bfloat16(v.y);
        b.x = __float2bfloat16(v.z); b.y = __float2bfloat16(v.w);
        bf162* o = (bf162*)(out + idx);
        o[0] = a; o[1] = b;
    }
}

__global__ void pack3b(const float* __restrict__ bk, const float* __restrict__ bq,
                       const float* __restrict__ bv, float* __restrict__ out, int Fo) {
    int total = TT * 3 * Fo;
    for (int i = blockIdx.x * blockDim.x + threadIdx.x; i < total; i += gridDim.x * blockDim.x) {
        int j = i % (3 * Fo), t = i / (3 * Fo);
        int m = j / Fo, c = j % Fo;
        const float* b = (m == 0) ? bk : ((m == 1) ? bq : bv);
        out[i] = b[t * Fo + c];
    }
}

__global__ void fill_f4(float4* p, int n4) {
    int i = blockIdx.x * blockDim.x + threadIdx.x;
    int stride = gridDim.x * blockDim.x;
    float4 z = make_float4(0.f, 0.f, 0.f, 0.f);
    for (; i < n4; i += stride) p[i] = z;
}

// ---------------- WIDE bf16 GEMM: 128x256x32, warp tile 64x64, 3-stage ----------------
// C[z](bf16)[M,Nn] = A[z][M,K] @ B[z][K,Nn] + bias[z]; lda=K, ldb=ldc=Nn; Nn % 256 == 0.
#define WSTAGES 3
#define WA_BYTES (128 * 40 * 2)
#define WB_BYTES (32 * 264 * 2)
#define WSMEM_BYTES (WSTAGES * (WA_BYTES + WB_BYTES))

__global__ __launch_bounds__(256, 1)
void gemm_wide(const bf16* __restrict__ A, const bf16* __restrict__ B,
               const float* __restrict__ bias, bf16* __restrict__ C,
               int M, int Nn, int K,
               size_t sA, size_t sB, size_t sBias, size_t sC)
{
    extern __shared__ char dynsmem[];
    bf16 (*As)[128][40] = (bf16(*)[128][40])dynsmem;
    bf16 (*Bs)[32][264] = (bf16(*)[32][264])(dynsmem + WSTAGES * WA_BYTES);

    int z = blockIdx.z;
    A += (size_t)z * sA;
    B += (size_t)z * sB;
    C += (size_t)z * sC;
    bias += (size_t)z * sBias;

    int bm = blockIdx.y * 128, bn = blockIdx.x * 256;
    int tid = threadIdx.x;
    int lane = tid & 31;
    int w = tid >> 5;
    int wm = (w & 1) * 64;
    int wn = (w >> 1) * 64;
    int tg = lane & 3;
    int rowg = lane >> 2;

    float acc[4][8][4];
#pragma unroll
    for (int i = 0; i < 4; i++)
#pragma unroll
        for (int j = 0; j < 8; j++)
#pragma unroll
            for (int r = 0; r < 4; r++) acc[i][j][r] = 0.f;

    const int nk = K / 32;

#define WLOAD(kt, s)                                                                   \
    do {                                                                               \
        _Pragma("unroll")                                                              \
        for (int p = 0; p < 2; p++) {                                                  \
            int idx = tid + p * 256;                                                   \
            int m = idx >> 2, c = (idx & 3) * 8;                                       \
            int gm = bm + m;                                                           \
            const bf16* sp = A + (size_t)(gm < M ? gm : 0) * K + (kt) + c;             \
            cp16(smem_u32(&As[s][m][c]), sp, gm < M ? 16 : 0);                         \
        }                                                                              \
        _Pragma("unroll")                                                              \
        for (int p = 0; p < 4; p++) {                                                  \
            int idx = tid + p * 256;                                                   \
            int kr = idx >> 5, c = (idx & 31) * 8;                                     \
            const bf16* sp = B + (size_t)((kt) + kr) * Nn + bn + c;                    \
            cp16(smem_u32(&Bs[s][kr][c]), sp, 16);                                     \
        }                                                                              \
    } while (0)

    WLOAD(0, 0); cp_commit();
    if (nk > 1) { WLOAD(32, 1); cp_commit(); }

    for (int it = 0; it < nk; it++) {
        cp_wait<1>();
        __syncthreads();
        int nxt = it + 2;
        if (nxt < nk) WLOAD(nxt * 32, nxt % WSTAGES);
        cp_commit();

        int cur = it % WSTAGES;
#pragma unroll
        for (int ks = 0; ks < 2; ks++) {
            int k0 = ks * 16;
            uint32_t af[4][4], bfr[8][2];
#pragma unroll
            for (int mt = 0; mt < 4; mt++) {
                int row = wm + mt * 16 + (lane & 15);
                int coff = k0 + ((lane >> 4) << 3);
                ldsm4(af[mt][0], af[mt][1], af[mt][2], af[mt][3],
                      smem_u32(&As[cur][row][coff]));
            }
#pragma unroll
            for (int ntp = 0; ntp < 4; ntp++) {
                int row = k0 + (lane & 7) + ((lane >> 3) & 1) * 8;
                int col = wn + ntp * 16 + ((lane >> 4) << 3);
                uint32_t r0, r1, r2, r3;
                ldsm4t(r0, r1, r2, r3, smem_u32(&Bs[cur][row][col]));
                bfr[ntp * 2][0] = r0; bfr[ntp * 2][1] = r1;
                bfr[ntp * 2 + 1][0] = r2; bfr[ntp * 2 + 1][1] = r3;
            }
#pragma unroll
            for (int mt = 0; mt < 4; mt++)
#pragma unroll
                for (int nt = 0; nt < 8; nt++)
                    mma_bf16(acc[mt][nt], af[mt], bfr[nt]);
        }
        __syncthreads();
    }
#undef WLOAD

#pragma unroll
    for (int mt = 0; mt < 4; mt++) {
#pragma unroll
        for (int nt = 0; nt < 8; nt++) {
            int gm0 = bm + wm + mt * 16 + rowg;
            int gn0 = bn + wn + nt * 8 + tg * 2;
            float b0 = bias[gn0], b1 = bias[gn0 + 1];
            if (gm0 < M) {
                bf162 v;
                v.x = __float2bfloat16(acc[mt][nt][0] + b0);
                v.y = __float2bfloat16(acc[mt][nt][1] + b1);
                *(bf162*)(C + (size_t)gm0 * Nn + gn0) = v;
            }
            if (gm0 + 8 < M) {
                bf162 v;
                v.x = __float2bfloat16(acc[mt][nt][2] + b0);
                v.y = __float2bfloat16(acc[mt][nt][3] + b1);
                *(bf162*)(C + (size_t)(gm0 + 8) * Nn + gn0) = v;
            }
        }
    }
}

// ---------------- 128x128 bf16 GEMM (rel transforms), 4-stage ----------------
#define GSTAGES 4
#define GSMEM_BYTES (GSTAGES * (128 * 40 + 32 * 136) * 2)

__global__ __launch_bounds__(256, 2)
void gemm_bf(const bf16* __restrict__ A, const bf16* __restrict__ B,
             const float* __restrict__ bias, bf16* __restrict__ C,
             int M, int Nn, int K, int lda, int ldb, int ldc,
             size_t sA, size_t sA2, size_t sB, size_t sB2,
             size_t sBias, size_t sC, size_t sC2)
{
    extern __shared__ char dynsmem[];
    bf16 (*As)[128][40] = (bf16(*)[128][40])dynsmem;
    bf16 (*Bs)[32][136] = (bf16(*)[32][136])(dynsmem + GSTAGES * 128 * 40 * 2);

    int z = blockIdx.z;
    int zl = z & 7, zh = z >> 3;
    A += (size_t)zl * sA + (size_t)zh * sA2;
    B += (size_t)zl * sB + (size_t)zh * sB2;
    C += (size_t)zl * sC + (size_t)zh * sC2;
    if (bias) bias += (size_t)zl * sBias;

    int bm = blockIdx.y * 128, bn = blockIdx.x * 128;
    int tid = threadIdx.x;
    int lane = tid & 31;
    int w = tid >> 5;
    int wm = (w & 1) * 64;
    int wn = (w >> 1) * 32;
    int tg = lane & 3;
    int rowg = lane >> 2;

    float acc[4][4][4];
#pragma unroll
    for (int i = 0; i < 4; i++)
#pragma unroll
        for (int j = 0; j < 4; j++)
#pragma unroll
            for (int r = 0; r < 4; r++) acc[i][j][r] = 0.f;

    const int nk = K / 32;

#define GLOAD(kt, s)                                                                   \
    do {                                                                               \
        _Pragma("unroll")                                                              \
        for (int p = 0; p < 2; p++) {                                                  \
            int idx = tid + p * 256;                                                   \
            int m = idx >> 2, c = (idx & 3) * 8;                                       \
            int gm = bm + m;                                                           \
            const bf16* sp = A + (size_t)(gm < M ? gm : 0) * lda + (kt) + c;           \
            cp16(smem_u32(&As[s][m][c]), sp, gm < M ? 16 : 0);                         \
        }                                                                              \
        _Pragma("unroll")                                                              \
        for (int p = 0; p < 2; p++) {                                                  \
            int idx = tid + p * 256;                                                   \
            int kr = idx >> 4, c = (idx & 15) * 8;                                     \
            int gn = bn + c;                                                           \
            const bf16* sp = B + (size_t)((kt) + kr) * ldb + (gn < Nn ? gn : 0);       \
            cp16(smem_u32(&Bs[s][kr][c]), sp, gn < Nn ? 16 : 0);                       \
        }                                                                              \
    } while (0)

#pragma unroll
    for (int s = 0; s < GSTAGES - 1; s++) {
        if (s < nk) GLOAD(s * 32, s);
        cp_commit();
    }

    for (int it = 0; it < nk; it++) {
        cp_wait<GSTAGES - 2>();
        __syncthreads();
        int nxt = it + GSTAGES - 1;
        int slot = nxt % GSTAGES;
        if (nxt < nk) GLOAD(nxt * 32, slot);
        cp_commit();

        int cur = it % GSTAGES;
#pragma unroll
        for (int ks = 0; ks < 2; ks++) {
            int k0 = ks * 16;
            uint32_t af[4][4], bfr[4][2];
#pragma unroll
            for (int mt = 0; mt < 4; mt++) {
                int row = wm + mt * 16 + (lane & 15);
                int coff = k0 + ((lane >> 4) << 3);
                ldsm4(af[mt][0], af[mt][1], af[mt][2], af[mt][3],
                      smem_u32(&As[cur][row][coff]));
            }
#pragma unroll
            for (int ntp = 0; ntp < 2; ntp++) {
                int row = k0 + (lane & 7) + ((lane >> 3) & 1) * 8;
                int col = wn + ntp * 16 + ((lane >> 4) << 3);
                uint32_t r0, r1, r2, r3;
                ldsm4t(r0, r1, r2, r3, smem_u32(&Bs[cur][row][col]));
                bfr[ntp * 2][0] = r0; bfr[ntp * 2][1] = r1;
                bfr[ntp * 2 + 1][0] = r2; bfr[ntp * 2 + 1][1] = r3;
            }
#pragma unroll
            for (int mt = 0; mt < 4; mt++)
#pragma unroll
                for (int nt = 0; nt < 4; nt++)
                    mma_bf16(acc[mt][nt], af[mt], bfr[nt]);
        }
    }
#undef GLOAD

#pragma unroll
    for (int mt = 0; mt < 4; mt++) {
#pragma unroll
        for (int nt = 0; nt < 4; nt++) {
            int gm0 = bm + wm + mt * 16 + rowg;
            int gn0 = bn + wn + nt * 8 + tg * 2;
            if (gn0 >= Nn) continue;
            float b0 = 0.f, b1 = 0.f;
            if (bias) { b0 = bias[gn0]; b1 = bias[gn0 + 1]; }
            if (gm0 < M) {
                bf162 v;
                v.x = __float2bfloat16(acc[mt][nt][0] + b0);
                v.y = __float2bfloat16(acc[mt][nt][1] + b1);
                *(bf162*)(C + (size_t)gm0 * ldc + gn0) = v;
            }
            if (gm0 + 8 < M) {
                bf162 v;
                v.x = __float2bfloat16(acc[mt][nt][2] + b0);
                v.y = __float2bfloat16(acc[mt][nt][3] + b1);
                *(bf162*)(C + (size_t)(gm0 + 8) * ldc + gn0) = v;
            }
        }
    }
}

// ---------------- fused edge kernel: warp per (edge, head) ----------------
template<int D>
__global__ void edge_fused(const bf16* __restrict__ q, int ldq,
                           const bf16* __restrict__ kr,
                           const bf16* __restrict__ vr, int ldf,
                           const int* __restrict__ src, const int* __restrict__ dst,
                           const float* __restrict__ prel_row,
                           float* __restrict__ sbuf, float* __restrict__ oute,
                           float scale)
{
    int warp = (blockIdx.x * blockDim.x + threadIdx.x) >> 5;
    int lane = threadIdx.x & 31;
    if (warp >= EE * NH) return;
    int ed = warp / NH, h = warp % NH;
    int sN = src[ed], dN = dst[ed];
    const bf162* qp = (const bf162*)(q + (size_t)dN * ldq + h * D);
    const bf162* kp = (const bf162*)(kr + (size_t)sN * ldf + h * D);
    const bf162* vp = (const bf162*)(vr + (size_t)sN * ldf + h * D);

    float acc;
    float4 vv;
    if (D == 128) {
        bf162 q0 = qp[lane * 2], q1 = qp[lane * 2 + 1];
        bf162 k0 = kp[lane * 2], k1 = kp[lane * 2 + 1];
        bf162 v0 = vp[lane * 2], v1 = vp[lane * 2 + 1];
        float2 a0 = __bfloat1622float2(q0), a1 = __bfloat1622float2(q1);
        float2 b0 = __bfloat1622float2(k0), b1 = __bfloat1622float2(k1);
        float2 c0 = __bfloat1622float2(v0), c1 = __bfloat1622float2(v1);
        acc = a0.x * b0.x + a0.y * b0.y + a1.x * b1.x + a1.y * b1.y;
        vv = make_float4(c0.x, c0.y, c1.x, c1.y);
    } else {
        bf162 q0 = qp[lane], k0 = kp[lane], v0 = vp[lane];
        float2 a = __bfloat1622float2(q0);
        float2 b = __bfloat1622float2(k0);
        float2 c = __bfloat1622float2(v0);
        acc = a.x * b.x + a.y * b.y;
        vv = make_float4(c.x, c.y, 0.f, 0.f);
    }
#pragma unroll
    for (int o = 16; o; o >>= 1) acc += __shfl_xor_sync(0xFFFFFFFFu, acc, o);
    float ex = expf(acc * prel_row[h] * scale);
    if (lane == 0) atomicAdd(&sbuf[(size_t)dN * NH + h], ex);
    float* op = oute + (size_t)dN * ldf + h * D;
    if (D == 128) {
        atomicAdd((float4*)(op + lane * 4),
                  make_float4(vv.x * ex, vv.y * ex, vv.z * ex, vv.w * ex));
    } else {
        atomicAdd((float2*)(op + lane * 2), make_float2(vv.x * ex, vv.y * ex));
    }
}

// ---------------- combine two edge-type buffers: normalize + gelu -> bf16 ----------------
template<int D>
__global__ void combine_gelu(const float* __restrict__ in0, const float* __restrict__ in1,
                             const float* __restrict__ s0, const float* __restrict__ s1,
                             bf16* __restrict__ out, int total, int F)
{
    int i4 = blockIdx.x * blockDim.x + threadIdx.x;
    int stride = gridDim.x * blockDim.x;
    int n4 = total / 4;
    for (; i4 < n4; i4 += stride) {
        int i = i4 * 4;
        int node = i / F;
        int h = (i % F) / D;
        float inv0 = 1.f / (s0[node * NH + h] + 1e-16f);
        float inv1 = 1.f / (s1[node * NH + h] + 1e-16f);
        float4 a = ((const float4*)in0)[i4];
        float4 b = ((const float4*)in1)[i4];
        float x0 = a.x * inv0 + b.x * inv1;
        float x1 = a.y * inv0 + b.y * inv1;
        float x2 = a.z * inv0 + b.z * inv1;
        float x3 = a.w * inv0 + b.w * inv1;
        bf162 r0, r1;
        r0.x = __float2bfloat16(0.5f * x0 * (1.0f + erff(x0 * 0.70710678f)));
        r0.y = __float2bfloat16(0.5f * x1 * (1.0f + erff(x1 * 0.70710678f)));
        r1.x = __float2bfloat16(0.5f * x2 * (1.0f + erff(x2 * 0.70710678f)));
        r1.y = __float2bfloat16(0.5f * x3 * (1.0f + erff(x3 * 0.70710678f)));
        ((bf162*)(out + i))[0] = r0;
        ((bf162*)(out + i))[1] = r1;
    }
}

// ---------------- final linear + row softmax (bf16 h2) ----------------
__global__ void final_kernel(const bf16* __restrict__ h2, const float* __restrict__ W,
                             const float* __restrict__ b, float* __restrict__ out)
{
    int warp = (blockIdx.x * blockDim.x + threadIdx.x) >> 5;
    int lane = threadIdx.x & 31;
    if (warp >= TT * NN) return;
    const bf16* hp = h2 + (size_t)warp * F2;
    float acc[OUTF];
#pragma unroll
    for (int o = 0; o < OUTF; o++) acc[o] = 0.f;
    for (int f = lane; f < F2; f += 32) {
        float xv = __bfloat162float(hp[f]);
        const float* wp = W + (size_t)f * OUTF;
#pragma unroll
        for (int o = 0; o < OUTF; o++) acc[o] = fmaf(xv, wp[o], acc[o]);
    }
#pragma unroll
    for (int o = 0; o < OUTF; o++) {
#pragma unroll
        for (int off = 16; off; off >>= 1) acc[o] += __shfl_down_sync(0xFFFFFFFFu, acc[o], off);
    }
    if (lane == 0) {
        float l[OUTF];
        float m = -1e30f;
#pragma unroll
        for (int o = 0; o < OUTF; o++) { l[o] = acc[o] + b[o]; m = fmaxf(m, l[o]); }
        float s = 0.f;
#pragma unroll
        for (int o = 0; o < OUTF; o++) { l[o] = expf(l[o] - m); s += l[o]; }
        float inv = 1.f / s;
        float* op = out + (size_t)warp * OUTF;
#pragma unroll
        for (int o = 0; o < OUTF; o++) op[o] = l[o] * inv;
    }
}

// ---------------- host launch helpers ----------------
static void gemm_big(const bf16* A, const bf16* B, const float* bias, bf16* C,
                     int M, int N, int K, size_t sA, size_t sB, size_t sBias, size_t sC)
{
    dim3 grid(N / 256, (M + 127) / 128, TT);
    gemm_wide<<<grid, 256, WSMEM_BYTES>>>(A, B, bias, C, M, N, K, sA, sB, sBias, sC);
}

static void gemm_rel(const bf16* A, const bf16* B, bf16* C,
                     int D, int F3, int F,
                     size_t sA2, size_t sB2, size_t sC2)
{
    dim3 grid(1, (NN + 127) / 128, 16);
    gemm_bf<<<grid, 256, GSMEM_BYTES>>>(A, B, nullptr, C, NN, D, D, F3, D, F,
                                        (size_t)D, sA2, (size_t)D * D, sB2,
                                        0, (size_t)D, sC2);
}

extern "C" void kernel_launch(void* const* d_in, const int* in_sizes, int n_in,
                              void* d_out, int out_size)
{
    (void)in_sizes; (void)n_in; (void)out_size;
    const float* x     = (const float*)d_in[0];
    const int* ei[4]   = {(const int*)d_in[1], (const int*)d_in[2],
                          (const int*)d_in[3], (const int*)d_in[4]};
    const float* Wk1 = (const float*)d_in[5];  const float* bk1 = (const float*)d_in[6];
    const float* Wq1 = (const float*)d_in[7];  const float* bq1 = (const float*)d_in[8];
    const float* Wv1 = (const float*)d_in[9];  const float* bv1 = (const float*)d_in[10];
    const float* Wa1 = (const float*)d_in[11]; const float* ba1 = (const float*)d_in[12];
    const float* arel1 = (const float*)d_in[13];
    const float* mrel1 = (const float*)d_in[14];
    const float* prel1 = (const float*)d_in[15];
    const float* Wk2 = (const float*)d_in[16]; const float* bk2 = (const float*)d_in[17];
    const float* Wq2 = (const float*)d_in[18]; const float* bq2 = (const float*)d_in[19];
    const float* Wv2 = (const float*)d_in[20]; const float* bv2 = (const float*)d_in[21];
    const float* Wa2 = (const float*)d_in[22]; const float* ba2 = (const float*)d_in[23];
    const float* arel2 = (const float*)d_in[24];
    const float* mrel2 = (const float*)d_in[25];
    const float* prel2 = (const float*)d_in[26];
    const float* Wlin = (const float*)d_in[27]; const float* blin = (const float*)d_in[28];
    float* out = (float*)d_out;

    cudaFuncSetAttribute(gemm_bf, cudaFuncAttributeMaxDynamicSharedMemorySize, GSMEM_BYTES);
    cudaFuncSetAttribute(gemm_wide, cudaFuncAttributeMaxDynamicSharedMemorySize, WSMEM_BYTES);

    bf16* BB = nullptr;
    float* FF = nullptr;
    cudaGetSymbolAddress((void**)&BB, g_bf);
    cudaGetSymbolAddress((void**)&FF, g_f32);

    bf16* XB = BB + OB_XB;
    bf16* WKQV1 = BB + OB_WKQV1; bf16* WA1B = BB + OB_WA1;
    bf16* AREL1B = BB + OB_AREL1; bf16* MREL1B = BB + OB_MREL1;
    bf16* WKQV2 = BB + OB_WKQV2; bf16* WA2B = BB + OB_WA2;
    bf16* AREL2B = BB + OB_AREL2; bf16* MREL2B = BB + OB_MREL2;
    bf16* KQV1 = BB + OB_KQV1; bf16* KR1 = BB + OB_KR1; bf16* VR1 = BB + OB_VR1;
    bf16* ACT1 = BB + OB_ACT1; bf16* H1 = BB + OB_H1;
    bf16* KQV2 = BB + OB_KQV2; bf16* KR2 = BB + OB_KR2; bf16* VR2 = BB + OB_VR2;
    bf16* ACT2 = BB + OB_ACT2; bf16* H2 = BB + OB_H2;

    float* OUTE = FF + OF_OUTE;
    float* SB = FF + OF_SB;
    float* BKQV1 = FF + OF_BKQV1; float* BKQV2 = FF + OF_BKQV2;

    const int st[4] = {0, 0, 1, 1};
    const int dt[4] = {0, 1, 0, 1};
    const int ewb = (EE * NH * 32 + 255) / 256;

    // ---- pre-pass (launch #4 = KQV1 GEMM, which is what ncu captures) ----
    cvt_bf4<<<2048, 256>>>(x, XB, (size_t)TT * NN * F0 / 4);                    // 1
    pack3w<<<2048, 256>>>(Wk1, Wq1, Wv1, WKQV1, F0, F1);                        // 2
    pack3b<<<24, 256>>>(bk1, bq1, bv1, BKQV1, F1);                              // 3

    // ============ LAYER 1 ============
    // 4 (profiled): fused K|Q|V projection [T,N,2048] @ [T,2048,3072]
    gemm_big(XB, WKQV1, BKQV1, KQV1, NN, 3 * F1, F0,
             (size_t)NN * F0, (size_t)F0 * 3 * F1, 3 * F1, (size_t)NN * 3 * F1);

    // remaining conversions
    cvt_bf4<<<512, 256>>>(arel1, AREL1B, (size_t)4 * NH * D1 * D1 / 4);
    cvt_bf4<<<512, 256>>>(mrel1, MREL1B, (size_t)4 * NH * D1 * D1 / 4);
    cvt_bf4<<<512, 256>>>(Wa1, WA1B, (size_t)TT * F1 * F1 / 4);
    pack3w<<<1024, 256>>>(Wk2, Wq2, Wv2, WKQV2, F1, F2);
    pack3b<<<12, 256>>>(bk2, bq2, bv2, BKQV2, F2);
    cvt_bf4<<<512, 256>>>(Wa2, WA2B, (size_t)TT * F2 * F2 / 4);
    cvt_bf4<<<128, 256>>>(arel2, AREL2B, (size_t)4 * NH * D2 * D2 / 4);
    cvt_bf4<<<128, 256>>>(mrel2, MREL2B, (size_t)4 * NH * D2 * D2 / 4);

    // rel transforms: one batch-16 launch per edge type
    for (int e = 0; e < 4; e++) {
        gemm_rel(KQV1 + (size_t)st[e] * NN * 3 * F1,
                 AREL1B + (size_t)e * NH * D1 * D1,
                 KR1 + (size_t)e * NN * F1,
                 D1, 3 * F1, F1,
                 (size_t)2 * F1, (size_t)4 * NH * D1 * D1, (size_t)4 * NN * F1);
    }

    fill_f4<<<512, 256>>>((float4*)SB, 4 * NN * NH / 4);
    fill_f4<<<2048, 256>>>((float4*)OUTE, 4 * NN * F1 / 4);
    {
        float scale = 1.f / sqrtf((float)D1);
        for (int e = 0; e < 4; e++)
            edge_fused<D1><<<ewb, 256>>>(KQV1 + (size_t)dt[e] * NN * 3 * F1 + F1, 3 * F1,
                KR1 + (size_t)e * NN * F1, VR1 + (size_t)e * NN * F1, F1,
                ei[e], ei[e] + EE, prel1 + e * NH,
                SB + (size_t)e * NN * NH, OUTE + (size_t)e * NN * F1, scale);
    }
    combine_gelu<D1><<<2048, 256>>>(OUTE, OUTE + (size_t)2 * NN * F1,
                                    SB, SB + (size_t)2 * NN * NH,
                                    ACT1, NN * F1, F1);
    combine_gelu<D1><<<2048, 256>>>(OUTE + (size_t)1 * NN * F1, OUTE + (size_t)3 * NN * F1,
                                    SB + (size_t)1 * NN * NH, SB + (size_t)3 * NN * NH,
                                    ACT1 + (size_t)NN * F1, NN * F1, F1);

    gemm_big(ACT1, WA1B, ba1, H1, NN, F1, F1,
             (size_t)NN * F1, (size_t)F1 * F1, F1, (size_t)NN * F1);

    // ============ LAYER 2 ============
    gemm_big(H1, WKQV2, BKQV2, KQV2, NN, 3 * F2, F1,
             (size_t)NN * F1, (size_t)F1 * 3 * F2, 3 * F2, (size_t)NN * 3 * F2);

    for (int e = 0; e < 4; e++) {
        gemm_rel(KQV2 + (size_t)st[e] * NN * 3 * F2,
                 AREL2B + (size_t)e * NH * D2 * D2,
                 KR2 + (size_t)e * NN * F2,
                 D2, 3 * F2, F2,
                 (size_t)2 * F2, (size_t)4 * NH * D2 * D2, (size_t)4 * NN * F2);
    }

    fill_f4<<<512, 256>>>((float4*)SB, 4 * NN * NH / 4);
    fill_f4<<<1024, 256>>>((float4*)OUTE, 4 * NN * F2 / 4);
    {
        float scale = 1.f / sqrtf((float)D2);
        for (int e = 0; e < 4; e++)
            edge_fused<D2><<<ewb, 256>>>(KQV2 + (size_t)dt[e] * NN * 3 * F2 + F2, 3 * F2,
                KR2 + (size_t)e * NN * F2, VR2 + (size_t)e * NN * F2, F2,
                ei[e], ei[e] + EE, prel2 + e * NH,
                SB + (size_t)e * NN * NH, OUTE + (size_t)e * NN * F2, scale);
    }
    combine_gelu<D2><<<1024, 256>>>(OUTE, OUTE + (size_t)2 * NN * F2,
                                    SB, SB + (size_t)2 * NN * NH,
                                    ACT2, NN * F2, F2);
    combine_gelu<D2><<<1024, 256>>>(OUTE + (size_t)1 * NN * F2, OUTE + (size_t)3 * NN * F2,
                                    SB + (size_t)1 * NN * NH, SB + (size_t)3 * NN * NH,
                                    ACT2 + (size_t)NN * F2, NN * F2, F2);

    gemm_big(ACT2, WA2B, ba2, H2, NN, F2, F2,
             (size_t)NN * F2, (size_t)F2 * F2, F2, (size_t)NN * F2);

    // ============ final ============
    final_kernel<<<(TT * NN * 32 + 255) / 256, 256>>>(H2, Wlin, blin, out);
}

// round 13
// speedup vs baseline: 1.1858x; 1.1858x over previous
#include <cuda_runtime.h>
#include <cuda_bf16.h>
#include <math.h>
#include <stdint.h>

// ---------------- problem constants ----------------
#define NN 10000
#define EE 60000
#define TT 2
#define NH 8
#define F0 2048
#define F1 1024
#define D1 128
#define F2 512
#define D2 64
#define OUTF 8

typedef __nv_bfloat16 bf16;
typedef __nv_bfloat162 bf162;

// ---------------- bf16 scratch offsets (elements) ----------------
#define OB_XB      ((size_t)0)                               // TT*NN*F0
#define OB_WKQV1   (OB_XB + (size_t)TT*NN*F0)                // TT*F0*3F1
#define OB_WA1     (OB_WKQV1 + (size_t)TT*F0*3*F1)
#define OB_AREL1   (OB_WA1 + (size_t)TT*F1*F1)
#define OB_MREL1   (OB_AREL1 + (size_t)4*NH*D1*D1)           // must follow AREL1
#define OB_WKQV2   (OB_MREL1 + (size_t)4*NH*D1*D1)
#define OB_WA2     (OB_WKQV2 + (size_t)TT*F1*3*F2)
#define OB_AREL2   (OB_WA2 + (size_t)TT*F2*F2)
#define OB_MREL2   (OB_AREL2 + (size_t)4*NH*D2*D2)           // must follow AREL2
#define OB_KQV1    (OB_MREL2 + (size_t)4*NH*D2*D2)           // TT*NN*3F1
#define OB_KR1     (OB_KQV1 + (size_t)TT*NN*3*F1)            // 4*NN*F1
#define OB_VR1     (OB_KR1 + (size_t)4*NN*F1)                // must follow KR1
#define OB_ACT1    (OB_VR1 + (size_t)4*NN*F1)                // TT*NN*F1
#define OB_H1      (OB_ACT1 + (size_t)TT*NN*F1)
#define OB_KQV2    (OB_H1 + (size_t)TT*NN*F1)                // TT*NN*3F2
#define OB_KR2     (OB_KQV2 + (size_t)TT*NN*3*F2)
#define OB_VR2     (OB_KR2 + (size_t)4*NN*F2)                // must follow KR2
#define OB_ACT2    (OB_VR2 + (size_t)4*NN*F2)
#define OB_H2      (OB_ACT2 + (size_t)TT*NN*F2)
#define OB_TOTAL   (OB_H2 + (size_t)TT*NN*F2)

__device__ bf16 g_bf[OB_TOTAL];

// ---------------- fp32 scratch ----------------
#define OF_OUTE   ((size_t)0)                                // 4*NN*F1
#define OF_SB     (OF_OUTE + (size_t)4*NN*F1)                // 4*NN*NH
#define OF_BKQV1  (OF_SB + (size_t)4*NN*NH)                  // TT*3F1
#define OF_BKQV2  (OF_BKQV1 + (size_t)TT*3*F1)               // TT*3F2
#define OF_TOTAL  (OF_BKQV2 + (size_t)TT*3*F2)

__device__ float g_f32[OF_TOTAL];

// ---------------- asm helpers ----------------
__device__ __forceinline__ uint32_t smem_u32(const void* p) {
    return (uint32_t)__cvta_generic_to_shared(p);
}
__device__ __forceinline__ void cp16(uint32_t dst, const void* src, int sz) {
    asm volatile("cp.async.cg.shared.global [%0], [%1], 16, %2;" :: "r"(dst), "l"(src), "r"(sz));
}
__device__ __forceinline__ void cp_commit() { asm volatile("cp.async.commit_group;"); }
template<int N> __device__ __forceinline__ void cp_wait() {
    asm volatile("cp.async.wait_group %0;" :: "n"(N));
}
__device__ __forceinline__ void ldsm4(uint32_t& r0, uint32_t& r1, uint32_t& r2, uint32_t& r3, uint32_t a) {
    asm volatile("ldmatrix.sync.aligned.m8n8.x4.shared.b16 {%0,%1,%2,%3}, [%4];"
                 : "=r"(r0), "=r"(r1), "=r"(r2), "=r"(r3) : "r"(a));
}
__device__ __forceinline__ void ldsm4t(uint32_t& r0, uint32_t& r1, uint32_t& r2, uint32_t& r3, uint32_t a) {
    asm volatile("ldmatrix.sync.aligned.m8n8.x4.trans.shared.b16 {%0,%1,%2,%3}, [%4];"
                 : "=r"(r0), "=r"(r1), "=r"(r2), "=r"(r3) : "r"(a));
}
__device__ __forceinline__ void mma_bf16(float* c, const uint32_t* a, const uint32_t* b) {
    asm volatile("mma.sync.aligned.m16n8k16.row.col.f32.bf16.bf16.f32 "
                 "{%0,%1,%2,%3}, {%4,%5,%6,%7}, {%8,%9}, {%0,%1,%2,%3};"
                 : "+f"(c[0]), "+f"(c[1]), "+f"(c[2]), "+f"(c[3])
                 : "r"(a[0]), "r"(a[1]), "r"(a[2]), "r"(a[3]), "r"(b[0]), "r"(b[1]));
}

// ---------------- conversion / pack kernels ----------------
__global__ void cvt_bf4(const float* __restrict__ in, bf16* __restrict__ out, size_t n4) {
    size_t stride = (size_t)gridDim.x * blockDim.x;
    for (size_t i = (size_t)blockIdx.x * blockDim.x + threadIdx.x; i < n4; i += stride) {
        float4 v = ((const float4*)in)[i];
        bf162 a, b;
        a.x = __float2bfloat16(v.x); a.y = __float2bfloat16(v.y);
        b.x = __float2bfloat16(v.z); b.y = __float2bfloat16(v.w);
        ((bf162*)out)[i * 2] = a;
        ((bf162*)out)[i * 2 + 1] = b;
    }
}

// pack 3 weight matrices [T,Kd,Fo] along N -> out [T,Kd,3*Fo] bf16
__global__ void pack3w(const float* __restrict__ Wk, const float* __restrict__ Wq,
                       const float* __restrict__ Wv, bf16* __restrict__ out, int Kd, int Fo) {
    size_t total4 = (size_t)TT * Kd * 3 * Fo / 4;
    size_t stride = (size_t)gridDim.x * blockDim.x;
    for (size_t i = (size_t)blockIdx.x * blockDim.x + threadIdx.x; i < total4; i += stride) {
        size_t idx = i * 4;
        int j = (int)(idx % (size_t)(3 * Fo));
        size_t tk = idx / (size_t)(3 * Fo);
        int m = j / Fo, c = j % Fo;
        const float* W = (m == 0) ? Wk : ((m == 1) ? Wq : Wv);
        float4 v = *(const float4*)(W + tk * Fo + c);
        bf162 a, b;
        a.x = __float2bfloat16(v.x); a.y = __float2bfloat16(v.y);
        b.x = __float2bfloat16(v.z); b.y = __float2bfloat16(v.w);
        bf162* o = (bf162*)(out + idx);
        o[0] = a; o[1] = b;
    }
}

__global__ void pack3b(const float* __restrict__ bk, const float* __restrict__ bq,
                       const float* __restrict__ bv, float* __restrict__ out, int Fo) {
    int total = TT * 3 * Fo;
    for (int i = blockIdx.x * blockDim.x + threadIdx.x; i < total; i += gridDim.x * blockDim.x) {
        int j = i % (3 * Fo), t = i / (3 * Fo);
        int m = j / Fo, c = j % Fo;
        const float* b = (m == 0) ? bk : ((m == 1) ? bq : bv);
        out[i] = b[t * Fo + c];
    }
}

__global__ void fill_f4(float4* p, int n4) {
    int i = blockIdx.x * blockDim.x + threadIdx.x;
    int stride = gridDim.x * blockDim.x;
    float4 z = make_float4(0.f, 0.f, 0.f, 0.f);
    for (; i < n4; i += stride) p[i] = z;
}

// ---------------- BIG bf16 GEMM: 128x128x32, 4 warps (64x64 each), 4-stage, 2 CTA/SM ----
// C[z](bf16)[M,Nn] = A[z][M,K] @ B[z][K,Nn] + bias[z]; lda=K, ldb=ldc=Nn; Nn % 128 == 0.
#define G2STAGES 4
#define G2SMEM_BYTES (G2STAGES * (128 * 40 + 32 * 136) * 2)

__global__ __launch_bounds__(128, 2)
void gemm_bf2(const bf16* __restrict__ A, const bf16* __restrict__ B,
              const float* __restrict__ bias, bf16* __restrict__ C,
              int M, int Nn, int K,
              size_t sA, size_t sB, size_t sBias, size_t sC)
{
    extern __shared__ char dynsmem[];
    bf16 (*As)[128][40] = (bf16(*)[128][40])dynsmem;
    bf16 (*Bs)[32][136] = (bf16(*)[32][136])(dynsmem + G2STAGES * 128 * 40 * 2);

    int z = blockIdx.z;
    A += (size_t)z * sA;
    B += (size_t)z * sB;
    C += (size_t)z * sC;
    bias += (size_t)z * sBias;

    int bm = blockIdx.y * 128, bn = blockIdx.x * 128;
    int tid = threadIdx.x;
    int lane = tid & 31;
    int w = tid >> 5;
    int wm = (w & 1) * 64;
    int wn = (w >> 1) * 64;
    int tg = lane & 3;
    int rowg = lane >> 2;

    float acc[4][8][4];
#pragma unroll
    for (int i = 0; i < 4; i++)
#pragma unroll
        for (int j = 0; j < 8; j++)
#pragma unroll
            for (int r = 0; r < 4; r++) acc[i][j][r] = 0.f;

    const int nk = K / 32;

#define G2LOAD(kt, s)                                                                  \
    do {                                                                               \
        _Pragma("unroll")                                                              \
        for (int p = 0; p < 4; p++) {                                                  \
            int idx = tid + p * 128;                                                   \
            int m = idx >> 2, c = (idx & 3) * 8;                                       \
            int gm = bm + m;                                                           \
            const bf16* sp = A + (size_t)(gm < M ? gm : 0) * K + (kt) + c;             \
            cp16(smem_u32(&As[s][m][c]), sp, gm < M ? 16 : 0);                         \
        }                                                                              \
        _Pragma("unroll")                                                              \
        for (int p = 0; p < 4; p++) {                                                  \
            int idx = tid + p * 128;                                                   \
            int kr = idx >> 4, c = (idx & 15) * 8;                                     \
            const bf16* sp = B + (size_t)((kt) + kr) * Nn + bn + c;                    \
            cp16(smem_u32(&Bs[s][kr][c]), sp, 16);                                     \
        }                                                                              \
    } while (0)

#pragma unroll
    for (int s = 0; s < G2STAGES - 1; s++) {
        if (s < nk) G2LOAD(s * 32, s);
        cp_commit();
    }

    for (int it = 0; it < nk; it++) {
        cp_wait<G2STAGES - 2>();
        __syncthreads();
        int nxt = it + G2STAGES - 1;
        if (nxt < nk) G2LOAD(nxt * 32, nxt % G2STAGES);
        cp_commit();

        int cur = it % G2STAGES;
#pragma unroll
        for (int ks = 0; ks < 2; ks++) {
            int k0 = ks * 16;
            uint32_t af[4][4], bfr[8][2];
#pragma unroll
            for (int mt = 0; mt < 4; mt++) {
                int row = wm + mt * 16 + (lane & 15);
                int coff = k0 + ((lane >> 4) << 3);
                ldsm4(af[mt][0], af[mt][1], af[mt][2], af[mt][3],
                      smem_u32(&As[cur][row][coff]));
            }
#pragma unroll
            for (int ntp = 0; ntp < 4; ntp++) {
                int row = k0 + (lane & 7) + ((lane >> 3) & 1) * 8;
                int col = wn + ntp * 16 + ((lane >> 4) << 3);
                uint32_t r0, r1, r2, r3;
                ldsm4t(r0, r1, r2, r3, smem_u32(&Bs[cur][row][col]));
                bfr[ntp * 2][0] = r0; bfr[ntp * 2][1] = r1;
                bfr[ntp * 2 + 1][0] = r2; bfr[ntp * 2 + 1][1] = r3;
            }
#pragma unroll
            for (int mt = 0; mt < 4; mt++)
#pragma unroll
                for (int nt = 0; nt < 8; nt++)
                    mma_bf16(acc[mt][nt], af[mt], bfr[nt]);
        }
    }
#undef G2LOAD

#pragma unroll
    for (int mt = 0; mt < 4; mt++) {
#pragma unroll
        for (int nt = 0; nt < 8; nt++) {
            int gm0 = bm + wm + mt * 16 + rowg;
            int gn0 = bn + wn + nt * 8 + tg * 2;
            float b0 = bias[gn0], b1 = bias[gn0 + 1];
            if (gm0 < M) {
                bf162 v;
                v.x = __float2bfloat16(acc[mt][nt][0] + b0);
                v.y = __float2bfloat16(acc[mt][nt][1] + b1);
                *(bf162*)(C + (size_t)gm0 * Nn + gn0) = v;
            }
            if (gm0 + 8 < M) {
                bf162 v;
                v.x = __float2bfloat16(acc[mt][nt][2] + b0);
                v.y = __float2bfloat16(acc[mt][nt][3] + b1);
                *(bf162*)(C + (size_t)(gm0 + 8) * Nn + gn0) = v;
            }
        }
    }
}

// ---------------- 128x128 bf16 GEMM (rel transforms), 4-stage, 256 thr ----------------
#define GSTAGES 4
#define GSMEM_BYTES (GSTAGES * (128 * 40 + 32 * 136) * 2)

__global__ __launch_bounds__(256, 2)
void gemm_bf(const bf16* __restrict__ A, const bf16* __restrict__ B,
             const float* __restrict__ bias, bf16* __restrict__ C,
             int M, int Nn, int K, int lda, int ldb, int ldc,
             size_t sA, size_t sA2, size_t sB, size_t sB2,
             size_t sBias, size_t sC, size_t sC2)
{
    extern __shared__ char dynsmem[];
    bf16 (*As)[128][40] = (bf16(*)[128][40])dynsmem;
    bf16 (*Bs)[32][136] = (bf16(*)[32][136])(dynsmem + GSTAGES * 128 * 40 * 2);

    int z = blockIdx.z;
    int zl = z & 7, zh = z >> 3;
    A += (size_t)zl * sA + (size_t)zh * sA2;
    B += (size_t)zl * sB + (size_t)zh * sB2;
    C += (size_t)zl * sC + (size_t)zh * sC2;
    if (bias) bias += (size_t)zl * sBias;

    int bm = blockIdx.y * 128, bn = blockIdx.x * 128;
    int tid = threadIdx.x;
    int lane = tid & 31;
    int w = tid >> 5;
    int wm = (w & 1) * 64;
    int wn = (w >> 1) * 32;
    int tg = lane & 3;
    int rowg = lane >> 2;

    float acc[4][4][4];
#pragma unroll
    for (int i = 0; i < 4; i++)
#pragma unroll
        for (int j = 0; j < 4; j++)
#pragma unroll
            for (int r = 0; r < 4; r++) acc[i][j][r] = 0.f;

    const int nk = K / 32;

#define GLOAD(kt, s)                                                                   \
    do {                                                                               \
        _Pragma("unroll")                                                              \
        for (int p = 0; p < 2; p++) {                                                  \
            int idx = tid + p * 256;                                                   \
            int m = idx >> 2, c = (idx & 3) * 8;                                       \
            int gm = bm + m;                                                           \
            const bf16* sp = A + (size_t)(gm < M ? gm : 0) * lda + (kt) + c;           \
            cp16(smem_u32(&As[s][m][c]), sp, gm < M ? 16 : 0);                         \
        }                                                                              \
        _Pragma("unroll")                                                              \
        for (int p = 0; p < 2; p++) {                                                  \
            int idx = tid + p * 256;                                                   \
            int kr = idx >> 4, c = (idx & 15) * 8;                                     \
            int gn = bn + c;                                                           \
            const bf16* sp = B + (size_t)((kt) + kr) * ldb + (gn < Nn ? gn : 0);       \
            cp16(smem_u32(&Bs[s][kr][c]), sp, gn < Nn ? 16 : 0);                       \
        }                                                                              \
    } while (0)

#pragma unroll
    for (int s = 0; s < GSTAGES - 1; s++) {
        if (s < nk) GLOAD(s * 32, s);
        cp_commit();
    }

    for (int it = 0; it < nk; it++) {
        cp_wait<GSTAGES - 2>();
        __syncthreads();
        int nxt = it + GSTAGES - 1;
        int slot = nxt % GSTAGES;
        if (nxt < nk) GLOAD(nxt * 32, slot);
        cp_commit();

        int cur = it % GSTAGES;
#pragma unroll
        for (int ks = 0; ks < 2; ks++) {
            int k0 = ks * 16;
            uint32_t af[4][4], bfr[4][2];
#pragma unroll
            for (int mt = 0; mt < 4; mt++) {
                int row = wm + mt * 16 + (lane & 15);
                int coff = k0 + ((lane >> 4) << 3);
                ldsm4(af[mt][0], af[mt][1], af[mt][2], af[mt][3],
                      smem_u32(&As[cur][row][coff]));
            }
#pragma unroll
            for (int ntp = 0; ntp < 2; ntp++) {
                int row = k0 + (lane & 7) + ((lane >> 3) & 1) * 8;
                int col = wn + ntp * 16 + ((lane >> 4) << 3);
                uint32_t r0, r1, r2, r3;
                ldsm4t(r0, r1, r2, r3, smem_u32(&Bs[cur][row][col]));
                bfr[ntp * 2][0] = r0; bfr[ntp * 2][1] = r1;
                bfr[ntp * 2 + 1][0] = r2; bfr[ntp * 2 + 1][1] = r3;
            }
#pragma unroll
            for (int mt = 0; mt < 4; mt++)
#pragma unroll
                for (int nt = 0; nt < 4; nt++)
                    mma_bf16(acc[mt][nt], af[mt], bfr[nt]);
        }
    }
#undef GLOAD

#pragma unroll
    for (int mt = 0; mt < 4; mt++) {
#pragma unroll
        for (int nt = 0; nt < 4; nt++) {
            int gm0 = bm + wm + mt * 16 + rowg;
            int gn0 = bn + wn + nt * 8 + tg * 2;
            if (gn0 >= Nn) continue;
            float b0 = 0.f, b1 = 0.f;
            if (bias) { b0 = bias[gn0]; b1 = bias[gn0 + 1]; }
            if (gm0 < M) {
                bf162 v;
                v.x = __float2bfloat16(acc[mt][nt][0] + b0);
                v.y = __float2bfloat16(acc[mt][nt][1] + b1);
                *(bf162*)(C + (size_t)gm0 * ldc + gn0) = v;
            }
            if (gm0 + 8 < M) {
                bf162 v;
                v.x = __float2bfloat16(acc[mt][nt][2] + b0);
                v.y = __float2bfloat16(acc[mt][nt][3] + b1);
                *(bf162*)(C + (size_t)(gm0 + 8) * ldc + gn0) = v;
            }
        }
    }
}

// ---------------- fused edge kernel: warp per (edge, head) ----------------
template<int D>
__global__ void edge_fused(const bf16* __restrict__ q, int ldq,
                           const bf16* __restrict__ kr,
                           const bf16* __restrict__ vr, int ldf,
                           const int* __restrict__ src, const int* __restrict__ dst,
                           const float* __restrict__ prel_row,
                           float* __restrict__ sbuf, float* __restrict__ oute,
                           float scale)
{
    int warp = (blockIdx.x * blockDim.x + threadIdx.x) >> 5;
    int lane = threadIdx.x & 31;
    if (warp >= EE * NH) return;
    int ed = warp / NH, h = warp % NH;
    int sN = src[ed], dN = dst[ed];
    const bf162* qp = (const bf162*)(q + (size_t)dN * ldq + h * D);
    const bf162* kp = (const bf162*)(kr + (size_t)sN * ldf + h * D);
    const bf162* vp = (const bf162*)(vr + (size_t)sN * ldf + h * D);

    float acc;
    float4 vv;
    if (D == 128) {
        bf162 q0 = qp[lane * 2], q1 = qp[lane * 2 + 1];
        bf162 k0 = kp[lane * 2], k1 = kp[lane * 2 + 1];
        bf162 v0 = vp[lane * 2], v1 = vp[lane * 2 + 1];
        float2 a0 = __bfloat1622float2(q0), a1 = __bfloat1622float2(q1);
        float2 b0 = __bfloat1622float2(k0), b1 = __bfloat1622float2(k1);
        float2 c0 = __bfloat1622float2(v0), c1 = __bfloat1622float2(v1);
        acc = a0.x * b0.x + a0.y * b0.y + a1.x * b1.x + a1.y * b1.y;
        vv = make_float4(c0.x, c0.y, c1.x, c1.y);
    } else {
        bf162 q0 = qp[lane], k0 = kp[lane], v0 = vp[lane];
        float2 a = __bfloat1622float2(q0);
        float2 b = __bfloat1622float2(k0);
        float2 c = __bfloat1622float2(v0);
        acc = a.x * b.x + a.y * b.y;
        vv = make_float4(c.x, c.y, 0.f, 0.f);
    }
#pragma unroll
    for (int o = 16; o; o >>= 1) acc += __shfl_xor_sync(0xFFFFFFFFu, acc, o);
    float ex = expf(acc * prel_row[h] * scale);
    if (lane == 0) atomicAdd(&sbuf[(size_t)dN * NH + h], ex);
    float* op = oute + (size_t)dN * ldf + h * D;
    if (D == 128) {
        atomicAdd((float4*)(op + lane * 4),
                  make_float4(vv.x * ex, vv.y * ex, vv.z * ex, vv.w * ex));
    } else {
        atomicAdd((float2*)(op + lane * 2), make_float2(vv.x * ex, vv.y * ex));
    }
}

// ---------------- combine two edge-type buffers: normalize + gelu -> bf16 ----------------
template<int D>
__global__ void combine_gelu(const float* __restrict__ in0, const float* __restrict__ in1,
                             const float* __restrict__ s0, const float* __restrict__ s1,
                             bf16* __restrict__ out, int total, int F)
{
    int i4 = blockIdx.x * blockDim.x + threadIdx.x;
    int stride = gridDim.x * blockDim.x;
    int n4 = total / 4;
    for (; i4 < n4; i4 += stride) {
        int i = i4 * 4;
        int node = i / F;
        int h = (i % F) / D;
        float inv0 = 1.f / (s0[node * NH + h] + 1e-16f);
        float inv1 = 1.f / (s1[node * NH + h] + 1e-16f);
        float4 a = ((const float4*)in0)[i4];
        float4 b = ((const float4*)in1)[i4];
        float x0 = a.x * inv0 + b.x * inv1;
        float x1 = a.y * inv0 + b.y * inv1;
        float x2 = a.z * inv0 + b.z * inv1;
        float x3 = a.w * inv0 + b.w * inv1;
        bf162 r0, r1;
        r0.x = __float2bfloat16(0.5f * x0 * (1.0f + erff(x0 * 0.70710678f)));
        r0.y = __float2bfloat16(0.5f * x1 * (1.0f + erff(x1 * 0.70710678f)));
        r1.x = __float2bfloat16(0.5f * x2 * (1.0f + erff(x2 * 0.70710678f)));
        r1.y = __float2bfloat16(0.5f * x3 * (1.0f + erff(x3 * 0.70710678f)));
        ((bf162*)(out + i))[0] = r0;
        ((bf162*)(out + i))[1] = r1;
    }
}

// ---------------- final linear + row softmax (bf16 h2) ----------------
__global__ void final_kernel(const bf16* __restrict__ h2, const float* __restrict__ W,
                             const float* __restrict__ b, float* __restrict__ out)
{
    int warp = (blockIdx.x * blockDim.x + threadIdx.x) >> 5;
    int lane = threadIdx.x & 31;
    if (warp >= TT * NN) return;
    const bf16* hp = h2 + (size_t)warp * F2;
    float acc[OUTF];
#pragma unroll
    for (int o = 0; o < OUTF; o++) acc[o] = 0.f;
    for (int f = lane; f < F2; f += 32) {
        float xv = __bfloat162float(hp[f]);
        const float* wp = W + (size_t)f * OUTF;
#pragma unroll
        for (int o = 0; o < OUTF; o++) acc[o] = fmaf(xv, wp[o], acc[o]);
    }
#pragma unroll
    for (int o = 0; o < OUTF; o++) {
#pragma unroll
        for (int off = 16; off; off >>= 1) acc[o] += __shfl_down_sync(0xFFFFFFFFu, acc[o], off);
    }
    if (lane == 0) {
        float l[OUTF];
        float m = -1e30f;
#pragma unroll
        for (int o = 0; o < OUTF; o++) { l[o] = acc[o] + b[o]; m = fmaxf(m, l[o]); }
        float s = 0.f;
#pragma unroll
        for (int o = 0; o < OUTF; o++) { l[o] = expf(l[o] - m); s += l[o]; }
        float inv = 1.f / s;
        float* op = out + (size_t)warp * OUTF;
#pragma unroll
        for (int o = 0; o < OUTF; o++) op[o] = l[o] * inv;
    }
}

// ---------------- host launch helpers ----------------
static void gemm_big(const bf16* A, const bf16* B, const float* bias, bf16* C,
                     int M, int N, int K, size_t sA, size_t sB, size_t sBias, size_t sC)
{
    dim3 grid(N / 128, (M + 127) / 128, TT);
    gemm_bf2<<<grid, 128, G2SMEM_BYTES>>>(A, B, bias, C, M, N, K, sA, sB, sBias, sC);
}

static void gemm_rel(const bf16* A, const bf16* B, bf16* C,
                     int D, int F3, int F,
                     size_t sA2, size_t sB2, size_t sC2)
{
    dim3 grid(1, (NN + 127) / 128, 16);
    gemm_bf<<<grid, 256, GSMEM_BYTES>>>(A, B, nullptr, C, NN, D, D, F3, D, F,
                                        (size_t)D, sA2, (size_t)D * D, sB2,
                                        0, (size_t)D, sC2);
}

extern "C" void kernel_launch(void* const* d_in, const int* in_sizes, int n_in,
                              void* d_out, int out_size)
{
    (void)in_sizes; (void)n_in; (void)out_size;
    const float* x     = (const float*)d_in[0];
    const int* ei[4]   = {(const int*)d_in[1], (const int*)d_in[2],
                          (const int*)d_in[3], (const int*)d_in[4]};
    const float* Wk1 = (const float*)d_in[5];  const float* bk1 = (const float*)d_in[6];
    const float* Wq1 = (const float*)d_in[7];  const float* bq1 = (const float*)d_in[8];
    const float* Wv1 = (const float*)d_in[9];  const float* bv1 = (const float*)d_in[10];
    const float* Wa1 = (const float*)d_in[11]; const float* ba1 = (const float*)d_in[12];
    const float* arel1 = (const float*)d_in[13];
    const float* mrel1 = (const float*)d_in[14];
    const float* prel1 = (const float*)d_in[15];
    const float* Wk2 = (const float*)d_in[16]; const float* bk2 = (const float*)d_in[17];
    const float* Wq2 = (const float*)d_in[18]; const float* bq2 = (const float*)d_in[19];
    const float* Wv2 = (const float*)d_in[20]; const float* bv2 = (const float*)d_in[21];
    const float* Wa2 = (const float*)d_in[22]; const float* ba2 = (const float*)d_in[23];
    const float* arel2 = (const float*)d_in[24];
    const float* mrel2 = (const float*)d_in[25];
    const float* prel2 = (const float*)d_in[26];
    const float* Wlin = (const float*)d_in[27]; const float* blin = (const float*)d_in[28];
    float* out = (float*)d_out;

    cudaFuncSetAttribute(gemm_bf, cudaFuncAttributeMaxDynamicSharedMemorySize, GSMEM_BYTES);
    cudaFuncSetAttribute(gemm_bf2, cudaFuncAttributeMaxDynamicSharedMemorySize, G2SMEM_BYTES);

    bf16* BB = nullptr;
    float* FF = nullptr;
    cudaGetSymbolAddress((void**)&BB, g_bf);
    cudaGetSymbolAddress((void**)&FF, g_f32);

    bf16* XB = BB + OB_XB;
    bf16* WKQV1 = BB + OB_WKQV1; bf16* WA1B = BB + OB_WA1;
    bf16* AREL1B = BB + OB_AREL1; bf16* MREL1B = BB + OB_MREL1;
    bf16* WKQV2 = BB + OB_WKQV2; bf16* WA2B = BB + OB_WA2;
    bf16* AREL2B = BB + OB_AREL2; bf16* MREL2B = BB + OB_MREL2;
    bf16* KQV1 = BB + OB_KQV1; bf16* KR1 = BB + OB_KR1; bf16* VR1 = BB + OB_VR1;
    bf16* ACT1 = BB + OB_ACT1; bf16* H1 = BB + OB_H1;
    bf16* KQV2 = BB + OB_KQV2; bf16* KR2 = BB + OB_KR2; bf16* VR2 = BB + OB_VR2;
    bf16* ACT2 = BB + OB_ACT2; bf16* H2 = BB + OB_H2;

    float* OUTE = FF + OF_OUTE;
    float* SB = FF + OF_SB;
    float* BKQV1 = FF + OF_BKQV1; float* BKQV2 = FF + OF_BKQV2;

    const int st[4] = {0, 0, 1, 1};
    const int dt[4] = {0, 1, 0, 1};
    const int ewb = (EE * NH * 32 + 255) / 256;

    // ---- pre-pass (launch #4 = KQV1 GEMM, which is what ncu captures) ----
    cvt_bf4<<<2048, 256>>>(x, XB, (size_t)TT * NN * F0 / 4);                    // 1
    pack3w<<<2048, 256>>>(Wk1, Wq1, Wv1, WKQV1, F0, F1);                        // 2
    pack3b<<<24, 256>>>(bk1, bq1, bv1, BKQV1, F1);                              // 3

    // ============ LAYER 1 ============
    // 4 (profiled): fused K|Q|V projection [T,N,2048] @ [T,2048,3072]
    gemm_big(XB, WKQV1, BKQV1, KQV1, NN, 3 * F1, F0,
             (size_t)NN * F0, (size_t)F0 * 3 * F1, 3 * F1, (size_t)NN * 3 * F1);

    // remaining conversions
    cvt_bf4<<<512, 256>>>(arel1, AREL1B, (size_t)4 * NH * D1 * D1 / 4);
    cvt_bf4<<<512, 256>>>(mrel1, MREL1B, (size_t)4 * NH * D1 * D1 / 4);
    cvt_bf4<<<512, 256>>>(Wa1, WA1B, (size_t)TT * F1 * F1 / 4);
    pack3w<<<1024, 256>>>(Wk2, Wq2, Wv2, WKQV2, F1, F2);
    pack3b<<<12, 256>>>(bk2, bq2, bv2, BKQV2, F2);
    cvt_bf4<<<512, 256>>>(Wa2, WA2B, (size_t)TT * F2 * F2 / 4);
    cvt_bf4<<<128, 256>>>(arel2, AREL2B, (size_t)4 * NH * D2 * D2 / 4);
    cvt_bf4<<<128, 256>>>(mrel2, MREL2B, (size_t)4 * NH * D2 * D2 / 4);

    // rel transforms: one batch-16 launch per edge type
    for (int e = 0; e < 4; e++) {
        gemm_rel(KQV1 + (size_t)st[e] * NN * 3 * F1,
                 AREL1B + (size_t)e * NH * D1 * D1,
                 KR1 + (size_t)e * NN * F1,
                 D1, 3 * F1, F1,
                 (size_t)2 * F1, (size_t)4 * NH * D1 * D1, (size_t)4 * NN * F1);
    }

    fill_f4<<<512, 256>>>((float4*)SB, 4 * NN * NH / 4);
    fill_f4<<<2048, 256>>>((float4*)OUTE, 4 * NN * F1 / 4);
    {
        float scale = 1.f / sqrtf((float)D1);
        for (int e = 0; e < 4; e++)
            edge_fused<D1><<<ewb, 256>>>(KQV1 + (size_t)dt[e] * NN * 3 * F1 + F1, 3 * F1,
                KR1 + (size_t)e * NN * F1, VR1 + (size_t)e * NN * F1, F1,
                ei[e], ei[e] + EE, prel1 + e * NH,
                SB + (size_t)e * NN * NH, OUTE + (size_t)e * NN * F1, scale);
    }
    combine_gelu<D1><<<2048, 256>>>(OUTE, OUTE + (size_t)2 * NN * F1,
                                    SB, SB + (size_t)2 * NN * NH,
                                    ACT1, NN * F1, F1);
    combine_gelu<D1><<<2048, 256>>>(OUTE + (size_t)1 * NN * F1, OUTE + (size_t)3 * NN * F1,
                                    SB + (size_t)1 * NN * NH, SB + (size_t)3 * NN * NH,
                                    ACT1 + (size_t)NN * F1, NN * F1, F1);

    gemm_big(ACT1, WA1B, ba1, H1, NN, F1, F1,
             (size_t)NN * F1, (size_t)F1 * F1, F1, (size_t)NN * F1);

    // ============ LAYER 2 ============
    gemm_big(H1, WKQV2, BKQV2, KQV2, NN, 3 * F2, F1,
             (size_t)NN * F1, (size_t)F1 * 3 * F2, 3 * F2, (size_t)NN * 3 * F2);

    for (int e = 0; e < 4; e++) {
        gemm_rel(KQV2 + (size_t)st[e] * NN * 3 * F2,
                 AREL2B + (size_t)e * NH * D2 * D2,
                 KR2 + (size_t)e * NN * F2,
                 D2, 3 * F2, F2,
                 (size_t)2 * F2, (size_t)4 * NH * D2 * D2, (size_t)4 * NN * F2);
    }

    fill_f4<<<512, 256>>>((float4*)SB, 4 * NN * NH / 4);
    fill_f4<<<1024, 256>>>((float4*)OUTE, 4 * NN * F2 / 4);
    {
        float scale = 1.f / sqrtf((float)D2);
        for (int e = 0; e < 4; e++)
            edge_fused<D2><<<ewb, 256>>>(KQV2 + (size_t)dt[e] * NN * 3 * F2 + F2, 3 * F2,
                KR2 + (size_t)e * NN * F2, VR2 + (size_t)e * NN * F2, F2,
                ei[e], ei[e] + EE, prel2 + e * NH,
                SB + (size_t)e * NN * NH, OUTE + (size_t)e * NN * F2, scale);
    }
    combine_gelu<D2><<<1024, 256>>>(OUTE, OUTE + (size_t)2 * NN * F2,
                                    SB, SB + (size_t)2 * NN * NH,
                                    ACT2, NN * F2, F2);
    combine_gelu<D2><<<1024, 256>>>(OUTE + (size_t)1 * NN * F2, OUTE + (size_t)3 * NN * F2,
                                    SB + (size_t)1 * NN * NH, SB + (size_t)3 * NN * NH,
                                    ACT2 + (size_t)NN * F2, NN * F2, F2);

    gemm_big(ACT2, WA2B, ba2, H2, NN, F2, F2,
             (size_t)NN * F2, (size_t)F2 * F2, F2, (size_t)NN * F2);

    // ============ final ============
    final_kernel<<<(TT * NN * 32 + 255) / 256, 256>>>(H2, Wlin, blin, out);
}

// round 15
// speedup vs baseline: 1.3393x; 1.1294x over previous
#include <cuda_runtime.h>
#include <cuda_bf16.h>
#include <math.h>
#include <stdint.h>

// ---------------- problem constants ----------------
#define NN 10000
#define EE 60000
#define TT 2
#define NH 8
#define F0 2048
#define F1 1024
#define D1 128
#define F2 512
#define D2 64
#define OUTF 8

typedef __nv_bfloat16 bf16;
typedef __nv_bfloat162 bf162;

// ---------------- bf16 scratch offsets (elements) ----------------
#define OB_XB      ((size_t)0)
#define OB_WKQV1   (OB_XB + (size_t)TT*NN*F0)
#define OB_WA1     (OB_WKQV1 + (size_t)TT*F0*3*F1)
#define OB_AREL1   (OB_WA1 + (size_t)TT*F1*F1)
#define OB_MREL1   (OB_AREL1 + (size_t)4*NH*D1*D1)           // must follow AREL1
#define OB_WKQV2   (OB_MREL1 + (size_t)4*NH*D1*D1)
#define OB_WA2     (OB_WKQV2 + (size_t)TT*F1*3*F2)
#define OB_AREL2   (OB_WA2 + (size_t)TT*F2*F2)
#define OB_MREL2   (OB_AREL2 + (size_t)4*NH*D2*D2)           // must follow AREL2
#define OB_KQV1    (OB_MREL2 + (size_t)4*NH*D2*D2)
#define OB_KR1     (OB_KQV1 + (size_t)TT*NN*3*F1)
#define OB_VR1     (OB_KR1 + (size_t)4*NN*F1)                // must follow KR1
#define OB_ACT1    (OB_VR1 + (size_t)4*NN*F1)
#define OB_H1      (OB_ACT1 + (size_t)TT*NN*F1)
#define OB_KQV2    (OB_H1 + (size_t)TT*NN*F1)
#define OB_KR2     (OB_KQV2 + (size_t)TT*NN*3*F2)
#define OB_VR2     (OB_KR2 + (size_t)4*NN*F2)                // must follow KR2
#define OB_ACT2    (OB_VR2 + (size_t)4*NN*F2)
#define OB_H2      (OB_ACT2 + (size_t)TT*NN*F2)
#define OB_TOTAL   (OB_H2 + (size_t)TT*NN*F2)

__device__ bf16 g_bf[OB_TOTAL];

// ---------------- fp32 scratch ----------------
#define OF_ALPHA  ((size_t)0)                                // 4*EE*NH
#define OF_BKQV1  (OF_ALPHA + (size_t)4*EE*NH)               // TT*3F1
#define OF_BKQV2  (OF_BKQV1 + (size_t)TT*3*F1)               // TT*3F2
#define OF_TOTAL  (OF_BKQV2 + (size_t)TT*3*F2)

__device__ float g_f32[OF_TOTAL];

// ---------------- CSR scratch ----------------
__device__ int g_deg[4 * NN];          // histogram, then scatter cursor
__device__ int g_rowptr[4 * (NN + 1)];
__device__ int g_list[4 * EE];

// ---------------- asm helpers ----------------
__device__ __forceinline__ uint32_t smem_u32(const void* p) {
    return (uint32_t)__cvta_generic_to_shared(p);
}
__device__ __forceinline__ void cp16(uint32_t dst, const void* src, int sz) {
    asm volatile("cp.async.cg.shared.global [%0], [%1], 16, %2;" :: "r"(dst), "l"(src), "r"(sz));
}
__device__ __forceinline__ void cp_commit() { asm volatile("cp.async.commit_group;"); }
template<int N> __device__ __forceinline__ void cp_wait() {
    asm volatile("cp.async.wait_group %0;" :: "n"(N));
}
__device__ __forceinline__ void ldsm4(uint32_t& r0, uint32_t& r1, uint32_t& r2, uint32_t& r3, uint32_t a) {
    asm volatile("ldmatrix.sync.aligned.m8n8.x4.shared.b16 {%0,%1,%2,%3}, [%4];"
                 : "=r"(r0), "=r"(r1), "=r"(r2), "=r"(r3) : "r"(a));
}
__device__ __forceinline__ void ldsm4t(uint32_t& r0, uint32_t& r1, uint32_t& r2, uint32_t& r3, uint32_t a) {
    asm volatile("ldmatrix.sync.aligned.m8n8.x4.trans.shared.b16 {%0,%1,%2,%3}, [%4];"
                 : "=r"(r0), "=r"(r1), "=r"(r2), "=r"(r3) : "r"(a));
}
__device__ __forceinline__ void mma_bf16(float* c, const uint32_t* a, const uint32_t* b) {
    asm volatile("mma.sync.aligned.m16n8k16.row.col.f32.bf16.bf16.f32 "
                 "{%0,%1,%2,%3}, {%4,%5,%6,%7}, {%8,%9}, {%0,%1,%2,%3};"
                 : "+f"(c[0]), "+f"(c[1]), "+f"(c[2]), "+f"(c[3])
                 : "r"(a[0]), "r"(a[1]), "r"(a[2]), "r"(a[3]), "r"(b[0]), "r"(b[1]));
}

// ---------------- conversion / pack kernels ----------------
__global__ void cvt_bf4(const float* __restrict__ in, bf16* __restrict__ out, size_t n4) {
    size_t stride = (size_t)gridDim.x * blockDim.x;
    for (size_t i = (size_t)blockIdx.x * blockDim.x + threadIdx.x; i < n4; i += stride) {
        float4 v = ((const float4*)in)[i];
        bf162 a, b;
        a.x = __float2bfloat16(v.x); a.y = __float2bfloat16(v.y);
        b.x = __float2bfloat16(v.z); b.y = __float2bfloat16(v.w);
        ((bf162*)out)[i * 2] = a;
        ((bf162*)out)[i * 2 + 1] = b;
    }
}

__global__ void pack3w(const float* __restrict__ Wk, const float* __restrict__ Wq,
                       const float* __restrict__ Wv, bf16* __restrict__ out, int Kd, int Fo) {
    size_t total4 = (size_t)TT * Kd * 3 * Fo / 4;
    size_t stride = (size_t)gridDim.x * blockDim.x;
    for (size_t i = (size_t)blockIdx.x * blockDim.x + threadIdx.x; i < total4; i += stride) {
        size_t idx = i * 4;
        int j = (int)(idx % (size_t)(3 * Fo));
        size_t tk = idx / (size_t)(3 * Fo);
        int m = j / Fo, c = j % Fo;
        const float* W = (m == 0) ? Wk : ((m == 1) ? Wq : Wv);
        float4 v = *(const float4*)(W + tk * Fo + c);
        bf162 a, b;
        a.x = __float2bfloat16(v.x); a.y = __float2bfloat16(v.y);
        b.x = __float2bfloat16(v.z); b.y = __float2bfloat16(v.w);
        bf162* o = (bf162*)(out + idx);
        o[0] = a; o[1] = b;
    }
}

__global__ void pack3b(const float* __restrict__ bk, const float* __restrict__ bq,
                       const float* __restrict__ bv, float* __restrict__ out, int Fo) {
    int total = TT * 3 * Fo;
    for (int i = blockIdx.x * blockDim.x + threadIdx.x; i < total; i += gridDim.x * blockDim.x) {
        int j = i % (3 * Fo), t = i / (3 * Fo);
        int m = j / Fo, c = j % Fo;
        const float* b = (m == 0) ? bk : ((m == 1) ? bq : bv);
        out[i] = b[t * Fo + c];
    }
}

// ---------------- CSR build kernels ----------------
__global__ void zero_int(int* p, int n) {
    int i = blockIdx.x * blockDim.x + threadIdx.x;
    if (i < n) p[i] = 0;
}

__global__ void hist_edges(const int* __restrict__ d0, const int* __restrict__ d1,
                           const int* __restrict__ d2, const int* __restrict__ d3,
                           int* __restrict__ deg4)
{
    int idx = blockIdx.x * blockDim.x + threadIdx.x;
    if (idx >= 4 * EE) return;
    int t = idx / EE, e = idx % EE;
    int dn = (t == 0 ? d0 : (t == 1 ? d1 : (t == 2 ? d2 : d3)))[e];
    atomicAdd(&deg4[t * NN + dn], 1);
}

// one block per edge type: exclusive scan of deg -> rowptr; overwrites deg with
// the start positions (scatter cursor).
__global__ void scan_deg(int* __restrict__ deg4, int* __restrict__ rowptr4)
{
    int t = blockIdx.x;
    int* deg = deg4 + t * NN;
    int* rp = rowptr4 + t * (NN + 1);
    __shared__ int sums[256];
    int tid = threadIdx.x;
    const int CH = (NN + 255) / 256;
    int base = tid * CH;
    int s = 0;
    for (int i = 0; i < CH; i++) {
        int idx = base + i;
        if (idx < NN) s += deg[idx];
    }
    sums[tid] = s;
    __syncthreads();
    for (int off = 1; off < 256; off <<= 1) {
        int v = (tid >= off) ? sums[tid - off] : 0;
        __syncthreads();
        if (tid >= off) sums[tid] += v;
        __syncthreads();
    }
    int run = (tid == 0) ? 0 : sums[tid - 1];
    for (int i = 0; i < CH; i++) {
        int idx = base + i;
        if (idx < NN) {
            int d = deg[idx];
            rp[idx] = run;
            deg[idx] = run;   // cursor init (deg no longer needed)
            run += d;
        }
    }
    if (tid == 255) rp[NN] = sums[255];
}

__global__ void scatter_edges(const int* __restrict__ d0, const int* __restrict__ d1,
                              const int* __restrict__ d2, const int* __restrict__ d3,
                              int* __restrict__ cursor4, int* __restrict__ list4)
{
    int idx = blockIdx.x * blockDim.x + threadIdx.x;
    if (idx >= 4 * EE) return;
    int t = idx / EE, e = idx % EE;
    int dn = (t == 0 ? d0 : (t == 1 ? d1 : (t == 2 ? d2 : d3)))[e];
    int pos = atomicAdd(&cursor4[t * NN + dn], 1);
    list4[t * EE + pos] = e;
}

// ---------------- BIG bf16 GEMM: 128x128x32, 4 warps (64x64 each), 4-stage, 2 CTA/SM ----
#define G2STAGES 4
#define G2SMEM_BYTES (G2STAGES * (128 * 40 + 32 * 136) * 2)

__global__ __launch_bounds__(128, 2)
void gemm_bf2(const bf16* __restrict__ A, const bf16* __restrict__ B,
              const float* __restrict__ bias, bf16* __restrict__ C,
              int M, int Nn, int K,
              size_t sA, size_t sB, size_t sBias, size_t sC)
{
    extern __shared__ char dynsmem[];
    bf16 (*As)[128][40] = (bf16(*)[128][40])dynsmem;
    bf16 (*Bs)[32][136] = (bf16(*)[32][136])(dynsmem + G2STAGES * 128 * 40 * 2);

    int z = blockIdx.z;
    A += (size_t)z * sA;
    B += (size_t)z * sB;
    C += (size_t)z * sC;
    bias += (size_t)z * sBias;

    int bm = blockIdx.y * 128, bn = blockIdx.x * 128;
    int tid = threadIdx.x;
    int lane = tid & 31;
    int w = tid >> 5;
    int wm = (w & 1) * 64;
    int wn = (w >> 1) * 64;
    int tg = lane & 3;
    int rowg = lane >> 2;

    float acc[4][8][4];
#pragma unroll
    for (int i = 0; i < 4; i++)
#pragma unroll
        for (int j = 0; j < 8; j++)
#pragma unroll
            for (int r = 0; r < 4; r++) acc[i][j][r] = 0.f;

    const int nk = K / 32;

#define G2LOAD(kt, s)                                                                  \
    do {                                                                               \
        _Pragma("unroll")                                                              \
        for (int p = 0; p < 4; p++) {                                                  \
            int idx = tid + p * 128;                                                   \
            int m = idx >> 2, c = (idx & 3) * 8;                                       \
            int gm = bm + m;                                                           \
            const bf16* sp = A + (size_t)(gm < M ? gm : 0) * K + (kt) + c;             \
            cp16(smem_u32(&As[s][m][c]), sp, gm < M ? 16 : 0);                         \
        }                                                                              \
        _Pragma("unroll")                                                              \
        for (int p = 0; p < 4; p++) {                                                  \
            int idx = tid + p * 128;                                                   \
            int kr = idx >> 4, c = (idx & 15) * 8;                                     \
            const bf16* sp = B + (size_t)((kt) + kr) * Nn + bn + c;                    \
            cp16(smem_u32(&Bs[s][kr][c]), sp, 16);                                     \
        }                                                                              \
    } while (0)

#pragma unroll
    for (int s = 0; s < G2STAGES - 1; s++) {
        if (s < nk) G2LOAD(s * 32, s);
        cp_commit();
    }

    for (int it = 0; it < nk; it++) {
        cp_wait<G2STAGES - 2>();
        __syncthreads();
        int nxt = it + G2STAGES - 1;
        if (nxt < nk) G2LOAD(nxt * 32, nxt % G2STAGES);
        cp_commit();

        int cur = it % G2STAGES;
#pragma unroll
        for (int ks = 0; ks < 2; ks++) {
            int k0 = ks * 16;
            uint32_t af[4][4], bfr[8][2];
#pragma unroll
            for (int mt = 0; mt < 4; mt++) {
                int row = wm + mt * 16 + (lane & 15);
                int coff = k0 + ((lane >> 4) << 3);
                ldsm4(af[mt][0], af[mt][1], af[mt][2], af[mt][3],
                      smem_u32(&As[cur][row][coff]));
            }
#pragma unroll
            for (int ntp = 0; ntp < 4; ntp++) {
                int row = k0 + (lane & 7) + ((lane >> 3) & 1) * 8;
                int col = wn + ntp * 16 + ((lane >> 4) << 3);
                uint32_t r0, r1, r2, r3;
                ldsm4t(r0, r1, r2, r3, smem_u32(&Bs[cur][row][col]));
                bfr[ntp * 2][0] = r0; bfr[ntp * 2][1] = r1;
                bfr[ntp * 2 + 1][0] = r2; bfr[ntp * 2 + 1][1] = r3;
            }
#pragma unroll
            for (int mt = 0; mt < 4; mt++)
#pragma unroll
                for (int nt = 0; nt < 8; nt++)
                    mma_bf16(acc[mt][nt], af[mt], bfr[nt]);
        }
    }
#undef G2LOAD

#pragma unroll
    for (int mt = 0; mt < 4; mt++) {
#pragma unroll
        for (int nt = 0; nt < 8; nt++) {
            int gm0 = bm + wm + mt * 16 + rowg;
            int gn0 = bn + wn + nt * 8 + tg * 2;
            float b0 = bias[gn0], b1 = bias[gn0 + 1];
            if (gm0 < M) {
                bf162 v;
                v.x = __float2bfloat16(acc[mt][nt][0] + b0);
                v.y = __float2bfloat16(acc[mt][nt][1] + b1);
                *(bf162*)(C + (size_t)gm0 * Nn + gn0) = v;
            }
            if (gm0 + 8 < M) {
                bf162 v;
                v.x = __float2bfloat16(acc[mt][nt][2] + b0);
                v.y = __float2bfloat16(acc[mt][nt][3] + b1);
                *(bf162*)(C + (size_t)(gm0 + 8) * Nn + gn0) = v;
            }
        }
    }
}

// ---------------- 128x128 bf16 GEMM (rel transforms), 4-stage, 256 thr ----------------
#define GSTAGES 4
#define GSMEM_BYTES (GSTAGES * (128 * 40 + 32 * 136) * 2)

__global__ __launch_bounds__(256, 2)
void gemm_bf(const bf16* __restrict__ A, const bf16* __restrict__ B,
             const float* __restrict__ bias, bf16* __restrict__ C,
             int M, int Nn, int K, int lda, int ldb, int ldc,
             size_t sA, size_t sA2, size_t sB, size_t sB2,
             size_t sBias, size_t sC, size_t sC2)
{
    extern __shared__ char dynsmem[];
    bf16 (*As)[128][40] = (bf16(*)[128][40])dynsmem;
    bf16 (*Bs)[32][136] = (bf16(*)[32][136])(dynsmem + GSTAGES * 128 * 40 * 2);

    int z = blockIdx.z;
    int zl = z & 7, zh = z >> 3;
    A += (size_t)zl * sA + (size_t)zh * sA2;
    B += (size_t)zl * sB + (size_t)zh * sB2;
    C += (size_t)zl * sC + (size_t)zh * sC2;
    if (bias) bias += (size_t)zl * sBias;

    int bm = blockIdx.y * 128, bn = blockIdx.x * 128;
    int tid = threadIdx.x;
    int lane = tid & 31;
    int w = tid >> 5;
    int wm = (w & 1) * 64;
    int wn = (w >> 1) * 32;
    int tg = lane & 3;
    int rowg = lane >> 2;

    float acc[4][4][4];
#pragma unroll
    for (int i = 0; i < 4; i++)
#pragma unroll
        for (int j = 0; j < 4; j++)
#pragma unroll
            for (int r = 0; r < 4; r++) acc[i][j][r] = 0.f;

    const int nk = K / 32;

#define GLOAD(kt, s)                                                                   \
    do {                                                                               \
        _Pragma("unroll")                                                              \
        for (int p = 0; p < 2; p++) {                                                  \
            int idx = tid + p * 256;                                                   \
            int m = idx >> 2, c = (idx & 3) * 8;                                       \
            int gm = bm + m;                                                           \
            const bf16* sp = A + (size_t)(gm < M ? gm : 0) * lda + (kt) + c;           \
            cp16(smem_u32(&As[s][m][c]), sp, gm < M ? 16 : 0);                         \
        }                                                                              \
        _Pragma("unroll")                                                              \
        for (int p = 0; p < 2; p++) {                                                  \
            int idx = tid + p * 256;                                                   \
            int kr = idx >> 4, c = (idx & 15) * 8;                                     \
            int gn = bn + c;                                                           \
            const bf16* sp = B + (size_t)((kt) + kr) * ldb + (gn < Nn ? gn : 0);       \
            cp16(smem_u32(&Bs[s][kr][c]), sp, gn < Nn ? 16 : 0);                       \
        }                                                                              \
    } while (0)

#pragma unroll
    for (int s = 0; s < GSTAGES - 1; s++) {
        if (s < nk) GLOAD(s * 32, s);
        cp_commit();
    }

    for (int it = 0; it < nk; it++) {
        cp_wait<GSTAGES - 2>();
        __syncthreads();
        int nxt = it + GSTAGES - 1;
        int slot = nxt % GSTAGES;
        if (nxt < nk) GLOAD(nxt * 32, slot);
        cp_commit();

        int cur = it % GSTAGES;
#pragma unroll
        for (int ks = 0; ks < 2; ks++) {
            int k0 = ks * 16;
            uint32_t af[4][4], bfr[4][2];
#pragma unroll
            for (int mt = 0; mt < 4; mt++) {
                int row = wm + mt * 16 + (lane & 15);
                int coff = k0 + ((lane >> 4) << 3);
                ldsm4(af[mt][0], af[mt][1], af[mt][2], af[mt][3],
                      smem_u32(&As[cur][row][coff]));
            }
#pragma unroll
            for (int ntp = 0; ntp < 2; ntp++) {
                int row = k0 + (lane & 7) + ((lane >> 3) & 1) * 8;
                int col = wn + ntp * 16 + ((lane >> 4) << 3);
                uint32_t r0, r1, r2, r3;
                ldsm4t(r0, r1, r2, r3, smem_u32(&Bs[cur][row][col]));
                bfr[ntp * 2][0] = r0; bfr[ntp * 2][1] = r1;
                bfr[ntp * 2 + 1][0] = r2; bfr[ntp * 2 + 1][1] = r3;
            }
#pragma unroll
            for (int mt = 0; mt < 4; mt++)
#pragma unroll
                for (int nt = 0; nt < 4; nt++)
                    mma_bf16(acc[mt][nt], af[mt], bfr[nt]);
        }
    }
#undef GLOAD

#pragma unroll
    for (int mt = 0; mt < 4; mt++) {
#pragma unroll
        for (int nt = 0; nt < 4; nt++) {
            int gm0 = bm + wm + mt * 16 + rowg;
            int gn0 = bn + wn + nt * 8 + tg * 2;
            if (gn0 >= Nn) continue;
            float b0 = 0.f, b1 = 0.f;
            if (bias) { b0 = bias[gn0]; b1 = bias[gn0 + 1]; }
            if (gm0 < M) {
                bf162 v;
                v.x = __float2bfloat16(acc[mt][nt][0] + b0);
                v.y = __float2bfloat16(acc[mt][nt][1] + b1);
                *(bf162*)(C + (size_t)gm0 * ldc + gn0) = v;
            }
            if (gm0 + 8 < M) {
                bf162 v;
                v.x = __float2bfloat16(acc[mt][nt][2] + b0);
                v.y = __float2bfloat16(acc[mt][nt][3] + b1);
                *(bf162*)(C + (size_t)(gm0 + 8) * ldc + gn0) = v;
            }
        }
    }
}

// ---------------- edge logits: warp per edge, all 8 heads, no atomics ----------------
__device__ __forceinline__ float dot8(uint4 a, uint4 b) {
    const bf162* pa = (const bf162*)&a;
    const bf162* pb = (const bf162*)&b;
    float s = 0.f;
#pragma unroll
    for (int i = 0; i < 4; i++) {
        float2 fa = __bfloat1622float2(pa[i]);
        float2 fb = __bfloat1622float2(pb[i]);
        s = fmaf(fa.x, fb.x, s);
        s = fmaf(fa.y, fb.y, s);
    }
    return s;
}

template<int D>
__global__ void edge_logits(const bf16* __restrict__ q, int ldq,
                            const bf16* __restrict__ kr, int ldf,
                            const int* __restrict__ src, const int* __restrict__ dst,
                            const float* __restrict__ prel_row,
                            float* __restrict__ alpha, float scale)
{
    constexpr int VEC = D / 4;       // dims per lane (head = lane>>2 spans 4 lanes)
    constexpr int NV = VEC / 8;      // uint4 loads per lane
    int e = (blockIdx.x * blockDim.x + threadIdx.x) >> 5;
    int lane = threadIdx.x & 31;
    if (e >= EE) return;
    int sN = src[e], dN = dst[e];
    const uint4* qp = (const uint4*)(q + (size_t)dN * ldq) + lane * NV;
    const uint4* kp = (const uint4*)(kr + (size_t)sN * ldf) + lane * NV;

    float acc = 0.f;
#pragma unroll
    for (int i = 0; i < NV; i++) acc += dot8(qp[i], kp[i]);
    acc += __shfl_xor_sync(0xFFFFFFFFu, acc, 1);
    acc += __shfl_xor_sync(0xFFFFFFFFu, acc, 2);

    int h = lane >> 2;
    if ((lane & 3) == 0)
        alpha[(size_t)e * NH + h] = expf(acc * prel_row[h] * scale);
}

// ---------------- CSR gather: warp per (dst node, head) over TWO edge types ----------
// out = gelu( (sum_A ex*v)/(sum_A ex) + (sum_B ex*v)/(sum_B ex) ) as bf16
template<int D>
__global__ void edge_gather(const bf16* __restrict__ vrA, const bf16* __restrict__ vrB,
                            const float* __restrict__ alA, const float* __restrict__ alB,
                            const int* __restrict__ srcA, const int* __restrict__ srcB,
                            const int* __restrict__ rpA, const int* __restrict__ listA,
                            const int* __restrict__ rpB, const int* __restrict__ listB,
                            bf16* __restrict__ outp, int F)
{
    constexpr int PL = D / 32;       // dims per lane: 4 (D=128) or 2 (D=64)
    int w = (blockIdx.x * blockDim.x + threadIdx.x) >> 5;
    int lane = threadIdx.x & 31;
    if (w >= NN * NH) return;
    int node = w / NH, h = w % NH;
    size_t loff = (size_t)h * D + lane * PL;

    float accA[PL], accB[PL];
#pragma unroll
    for (int j = 0; j < PL; j++) { accA[j] = 0.f; accB[j] = 0.f; }
    float sA = 0.f, sB = 0.f;

    int bA = rpA[node], eA = rpA[node + 1];
    for (int i = bA; i < eA; i++) {
        int e = listA[i];
        float ex = alA[(size_t)e * NH + h];
        int s = srcA[e];
        const bf16* vp = vrA + (size_t)s * F + loff;
        if (PL == 4) {
            uint2 u = *(const uint2*)vp;
            float2 f0 = __bfloat1622float2(*(const bf162*)&u.x);
            float2 f1 = __bfloat1622float2(*(const bf162*)&u.y);
            accA[0] = fmaf(ex, f0.x, accA[0]);
            accA[1] = fmaf(ex, f0.y, accA[1]);
            accA[2] = fmaf(ex, f1.x, accA[2]);
            accA[3] = fmaf(ex, f1.y, accA[3]);
        } else {
            uint32_t u = *(const uint32_t*)vp;
            float2 f = __bfloat1622float2(*(const bf162*)&u);
            accA[0] = fmaf(ex, f.x, accA[0]);
            accA[1] = fmaf(ex, f.y, accA[1]);
        }
        sA += ex;
    }

    int bB = rpB[node], eB = rpB[node + 1];
    for (int i = bB; i < eB; i++) {
        int e = listB[i];
        float ex = alB[(size_t)e * NH + h];
        int s = srcB[e];
        const bf16* vp = vrB + (size_t)s * F + loff;
        if (PL == 4) {
            uint2 u = *(const uint2*)vp;
            float2 f0 = __bfloat1622float2(*(const bf162*)&u.x);
            float2 f1 = __bfloat1622float2(*(const bf162*)&u.y);
            accB[0] = fmaf(ex, f0.x, accB[0]);
            accB[1] = fmaf(ex, f0.y, accB[1]);
            accB[2] = fmaf(ex, f1.x, accB[2]);
            accB[3] = fmaf(ex, f1.y, accB[3]);
        } else {
            uint32_t u = *(const uint32_t*)vp;
            float2 f = __bfloat1622float2(*(const bf162*)&u);
            accB[0] = fmaf(ex, f.x, accB[0]);
            accB[1] = fmaf(ex, f.y, accB[1]);
        }
        sB += ex;
    }

    float invA = 1.f / (sA + 1e-16f);
    float invB = 1.f / (sB + 1e-16f);
    bf16* op = outp + (size_t)node * F + loff;
#pragma unroll
    for (int j = 0; j < PL; j += 2) {
        float x0 = accA[j] * invA + accB[j] * invB;
        float x1 = accA[j + 1] * invA + accB[j + 1] * invB;
        bf162 r;
        r.x = __float2bfloat16(0.5f * x0 * (1.0f + erff(x0 * 0.70710678f)));
        r.y = __float2bfloat16(0.5f * x1 * (1.0f + erff(x1 * 0.70710678f)));
        *(bf162*)(op + j) = r;
    }
}

// ---------------- final linear + row softmax (bf16 h2) ----------------
__global__ void final_kernel(const bf16* __restrict__ h2, const float* __restrict__ W,
                             const float* __restrict__ b, float* __restrict__ out)
{
    int warp = (blockIdx.x * blockDim.x + threadIdx.x) >> 5;
    int lane = threadIdx.x & 31;
    if (warp >= TT * NN) return;
    const bf16* hp = h2 + (size_t)warp * F2;
    float acc[OUTF];
#pragma unroll
    for (int o = 0; o < OUTF; o++) acc[o] = 0.f;
    for (int f = lane; f < F2; f += 32) {
        float xv = __bfloat162float(hp[f]);
        const float* wp = W + (size_t)f * OUTF;
#pragma unroll
        for (int o = 0; o < OUTF; o++) acc[o] = fmaf(xv, wp[o], acc[o]);
    }
#pragma unroll
    for (int o = 0; o < OUTF; o++) {
#pragma unroll
        for (int off = 16; off; off >>= 1) acc[o] += __shfl_down_sync(0xFFFFFFFFu, acc[o], off);
    }
    if (lane == 0) {
        float l[OUTF];
        float m = -1e30f;
#pragma unroll
        for (int o = 0; o < OUTF; o++) { l[o] = acc[o] + b[o]; m = fmaxf(m, l[o]); }
        float s = 0.f;
#pragma unroll
        for (int o = 0; o < OUTF; o++) { l[o] = expf(l[o] - m); s += l[o]; }
        float inv = 1.f / s;
        float* op = out + (size_t)warp * OUTF;
#pragma unroll
        for (int o = 0; o < OUTF; o++) op[o] = l[o] * inv;
    }
}

// ---------------- host launch helpers ----------------
static void gemm_big(const bf16* A, const bf16* B, const float* bias, bf16* C,
                     int M, int N, int K, size_t sA, size_t sB, size_t sBias, size_t sC)
{
    dim3 grid(N / 128, (M + 127) / 128, TT);
    gemm_bf2<<<grid, 128, G2SMEM_BYTES>>>(A, B, bias, C, M, N, K, sA, sB, sBias, sC);
}

static void gemm_rel(const bf16* A, const bf16* B, bf16* C,
                     int D, int F3, int F,
                     size_t sA2, size_t sB2, size_t sC2)
{
    dim3 grid(1, (NN + 127) / 128, 16);
    gemm_bf<<<grid, 256, GSMEM_BYTES>>>(A, B, nullptr, C, NN, D, D, F3, D, F,
                                        (size_t)D, sA2, (size_t)D * D, sB2,
                                        0, (size_t)D, sC2);
}

extern "C" void kernel_launch(void* const* d_in, const int* in_sizes, int n_in,
                              void* d_out, int out_size)
{
    (void)in_sizes; (void)n_in; (void)out_size;
    const float* x     = (const float*)d_in[0];
    const int* ei[4]   = {(const int*)d_in[1], (const int*)d_in[2],
                          (const int*)d_in[3], (const int*)d_in[4]};
    const float* Wk1 = (const float*)d_in[5];  const float* bk1 = (const float*)d_in[6];
    const float* Wq1 = (const float*)d_in[7];  const float* bq1 = (const float*)d_in[8];
    const float* Wv1 = (const float*)d_in[9];  const float* bv1 = (const float*)d_in[10];
    const float* Wa1 = (const float*)d_in[11]; const float* ba1 = (const float*)d_in[12];
    const float* arel1 = (const float*)d_in[13];
    const float* mrel1 = (const float*)d_in[14];
    const float* prel1 = (const float*)d_in[15];
    const float* Wk2 = (const float*)d_in[16]; const float* bk2 = (const float*)d_in[17];
    const float* Wq2 = (const float*)d_in[18]; const float* bq2 = (const float*)d_in[19];
    const float* Wv2 = (const float*)d_in[20]; const float* bv2 = (const float*)d_in[21];
    const float* Wa2 = (const float*)d_in[22]; const float* ba2 = (const float*)d_in[23];
    const float* arel2 = (const float*)d_in[24];
    const float* mrel2 = (const float*)d_in[25];
    const float* prel2 = (const float*)d_in[26];
    const float* Wlin = (const float*)d_in[27]; const float* blin = (const float*)d_in[28];
    float* out = (float*)d_out;

    cudaFuncSetAttribute(gemm_bf, cudaFuncAttributeMaxDynamicSharedMemorySize, GSMEM_BYTES);
    cudaFuncSetAttribute(gemm_bf2, cudaFuncAttributeMaxDynamicSharedMemorySize, G2SMEM_BYTES);

    bf16* BB = nullptr;
    float* FF = nullptr;
    int* DEG = nullptr; int* RP = nullptr; int* LST = nullptr;
    cudaGetSymbolAddress((void**)&BB, g_bf);
    cudaGetSymbolAddress((void**)&FF, g_f32);
    cudaGetSymbolAddress((void**)&DEG, g_deg);
    cudaGetSymbolAddress((void**)&RP, g_rowptr);
    cudaGetSymbolAddress((void**)&LST, g_list);

    bf16* XB = BB + OB_XB;
    bf16* WKQV1 = BB + OB_WKQV1; bf16* WA1B = BB + OB_WA1;
    bf16* AREL1B = BB + OB_AREL1; bf16* MREL1B = BB + OB_MREL1;
    bf16* WKQV2 = BB + OB_WKQV2; bf16* WA2B = BB + OB_WA2;
    bf16* AREL2B = BB + OB_AREL2; bf16* MREL2B = BB + OB_MREL2;
    bf16* KQV1 = BB + OB_KQV1; bf16* KR1 = BB + OB_KR1; bf16* VR1 = BB + OB_VR1;
    bf16* ACT1 = BB + OB_ACT1; bf16* H1 = BB + OB_H1;
    bf16* KQV2 = BB + OB_KQV2; bf16* KR2 = BB + OB_KR2; bf16* VR2 = BB + OB_VR2;
    bf16* ACT2 = BB + OB_ACT2; bf16* H2 = BB + OB_H2;

    float* ALPHA = FF + OF_ALPHA;
    float* BKQV1 = FF + OF_BKQV1; float* BKQV2 = FF + OF_BKQV2;

    const int st[4] = {0, 0, 1, 1};
    const int dt[4] = {0, 1, 0, 1};
    const int elb = (EE * 32 + 255) / 256;       // warp-per-edge logits
    const int ggb = (NN * NH * 32 + 255) / 256;  // warp-per-(node,head) gather
    const int ceb = (4 * EE + 255) / 256;

    const int* dp[4] = {ei[0] + EE, ei[1] + EE, ei[2] + EE, ei[3] + EE};

    // ---- pre-pass (launch #4 = KQV1 GEMM, which ncu captures) ----
    cvt_bf4<<<2048, 256>>>(x, XB, (size_t)TT * NN * F0 / 4);                    // 1
    pack3w<<<2048, 256>>>(Wk1, Wq1, Wv1, WKQV1, F0, F1);                        // 2
    pack3b<<<24, 256>>>(bk1, bq1, bv1, BKQV1, F1);                              // 3

    // ============ LAYER 1 ============
    // 4 (profiled): fused K|Q|V projection
    gemm_big(XB, WKQV1, BKQV1, KQV1, NN, 3 * F1, F0,
             (size_t)NN * F0, (size_t)F0 * 3 * F1, 3 * F1, (size_t)NN * 3 * F1);

    // CSR build (shared by both layers)
    zero_int<<<(4 * NN + 255) / 256, 256>>>(DEG, 4 * NN);
    hist_edges<<<ceb, 256>>>(dp[0], dp[1], dp[2], dp[3], DEG);
    scan_deg<<<4, 256>>>(DEG, RP);
    scatter_edges<<<ceb, 256>>>(dp[0], dp[1], dp[2], dp[3], DEG, LST);

    // remaining conversions
    cvt_bf4<<<512, 256>>>(arel1, AREL1B, (size_t)4 * NH * D1 * D1 / 4);
    cvt_bf4<<<512, 256>>>(mrel1, MREL1B, (size_t)4 * NH * D1 * D1 / 4);
    cvt_bf4<<<512, 256>>>(Wa1, WA1B, (size_t)TT * F1 * F1 / 4);
    pack3w<<<1024, 256>>>(Wk2, Wq2, Wv2, WKQV2, F1, F2);
    pack3b<<<12, 256>>>(bk2, bq2, bv2, BKQV2, F2);
    cvt_bf4<<<512, 256>>>(Wa2, WA2B, (size_t)TT * F2 * F2 / 4);
    cvt_bf4<<<128, 256>>>(arel2, AREL2B, (size_t)4 * NH * D2 * D2 / 4);
    cvt_bf4<<<128, 256>>>(mrel2, MREL2B, (size_t)4 * NH * D2 * D2 / 4);

    // rel transforms: one batch-16 launch per edge type
    for (int e = 0; e < 4; e++) {
        gemm_rel(KQV1 + (size_t)st[e] * NN * 3 * F1,
                 AREL1B + (size_t)e * NH * D1 * D1,
                 KR1 + (size_t)e * NN * F1,
                 D1, 3 * F1, F1,
                 (size_t)2 * F1, (size_t)4 * NH * D1 * D1, (size_t)4 * NN * F1);
    }

    // edge logits (no atomics)
    {
        float scale = 1.f / sqrtf((float)D1);
        for (int e = 0; e < 4; e++)
            edge_logits<D1><<<elb, 256>>>(KQV1 + (size_t)dt[e] * NN * 3 * F1 + F1, 3 * F1,
                KR1 + (size_t)e * NN * F1, F1, ei[e], ei[e] + EE, prel1 + e * NH,
                ALPHA + (size_t)e * EE * NH, scale);
    }
    // gather (dst type 0 <- e0,e2 ; dst type 1 <- e1,e3) -> ACT1 (gelu'd bf16)
    edge_gather<D1><<<ggb, 256>>>(VR1, VR1 + (size_t)2 * NN * F1,
        ALPHA, ALPHA + (size_t)2 * EE * NH, ei[0], ei[2],
        RP, LST, RP + 2 * (NN + 1), LST + 2 * EE, ACT1, F1);
    edge_gather<D1><<<ggb, 256>>>(VR1 + (size_t)1 * NN * F1, VR1 + (size_t)3 * NN * F1,
        ALPHA + (size_t)1 * EE * NH, ALPHA + (size_t)3 * EE * NH, ei[1], ei[3],
        RP + 1 * (NN + 1), LST + 1 * EE, RP + 3 * (NN + 1), LST + 3 * EE,
        ACT1 + (size_t)NN * F1, F1);

    gemm_big(ACT1, WA1B, ba1, H1, NN, F1, F1,
             (size_t)NN * F1, (size_t)F1 * F1, F1, (size_t)NN * F1);

    // ============ LAYER 2 ============
    gemm_big(H1, WKQV2, BKQV2, KQV2, NN, 3 * F2, F1,
             (size_t)NN * F1, (size_t)F1 * 3 * F2, 3 * F2, (size_t)NN * 3 * F2);

    for (int e = 0; e < 4; e++) {
        gemm_rel(KQV2 + (size_t)st[e] * NN * 3 * F2,
                 AREL2B + (size_t)e * NH * D2 * D2,
                 KR2 + (size_t)e * NN * F2,
                 D2, 3 * F2, F2,
                 (size_t)2 * F2, (size_t)4 * NH * D2 * D2, (size_t)4 * NN * F2);
    }

    {
        float scale = 1.f / sqrtf((float)D2);
        for (int e = 0; e < 4; e++)
            edge_logits<D2><<<elb, 256>>>(KQV2 + (size_t)dt[e] * NN * 3 * F2 + F2, 3 * F2,
                KR2 + (size_t)e * NN * F2, F2, ei[e], ei[e] + EE, prel2 + e * NH,
                ALPHA + (size_t)e * EE * NH, scale);
    }
    edge_gather<D2><<<ggb, 256>>>(VR2, VR2 + (size_t)2 * NN * F2,
        ALPHA, ALPHA + (size_t)2 * EE * NH, ei[0], ei[2],
        RP, LST, RP + 2 * (NN + 1), LST + 2 * EE, ACT2, F2);
    edge_gather<D2><<<ggb, 256>>>(VR2 + (size_t)1 * NN * F2, VR2 + (size_t)3 * NN * F2,
        ALPHA + (size_t)1 * EE * NH, ALPHA + (size_t)3 * EE * NH, ei[1], ei[3],
        RP + 1 * (NN + 1), LST + 1 * EE, RP + 3 * (NN + 1), LST + 3 * EE,
        ACT2 + (size_t)NN * F2, F2);

    gemm_big(ACT2, WA2B, ba2, H2, NN, F2, F2,
             (size_t)NN * F2, (size_t)F2 * F2, F2, (size_t)NN * F2);

    // ============ final ============
    final_kernel<<<(TT * NN * 32 + 255) / 256, 256>>>(H2, Wlin, blin, out);
}

// round 16
// speedup vs baseline: 1.3605x; 1.0158x over previous
#include <cuda_runtime.h>
#include <cuda_bf16.h>
#include <math.h>
#include <stdint.h>

// ---------------- problem constants ----------------
#define NN 10000
#define EE 60000
#define TT 2
#define NH 8
#define F0 2048
#define F1 1024
#define D1 128
#define F2 512
#define D2 64
#define OUTF 8

typedef __nv_bfloat16 bf16;
typedef __nv_bfloat162 bf162;

// ---------------- bf16 scratch offsets (elements) ----------------
// BP1/BP2: paired rel weights [mat(2)][st(2)][h(8)][D][2D]
// KR/VR:   paired layout [st(2)][NN][2F] (VR must follow KR at fixed offset)
#define OB_XB      ((size_t)0)
#define OB_WKQV1   (OB_XB + (size_t)TT*NN*F0)
#define OB_WA1     (OB_WKQV1 + (size_t)TT*F0*3*F1)
#define OB_BP1     (OB_WA1 + (size_t)TT*F1*F1)               // 2*2*8*D1*2*D1
#define OB_WKQV2   (OB_BP1 + (size_t)2*2*8*D1*2*D1)
#define OB_WA2     (OB_WKQV2 + (size_t)TT*F1*3*F2)
#define OB_BP2     (OB_WA2 + (size_t)TT*F2*F2)               // 2*2*8*D2*2*D2
#define OB_KQV1    (OB_BP2 + (size_t)2*2*8*D2*2*D2)
#define OB_KR1     (OB_KQV1 + (size_t)TT*NN*3*F1)            // 2*NN*2F1
#define OB_VR1     (OB_KR1 + (size_t)4*NN*F1)                // must follow KR1
#define OB_ACT1    (OB_VR1 + (size_t)4*NN*F1)
#define OB_H1      (OB_ACT1 + (size_t)TT*NN*F1)
#define OB_KQV2    (OB_H1 + (size_t)TT*NN*F1)
#define OB_KR2     (OB_KQV2 + (size_t)TT*NN*3*F2)
#define OB_VR2     (OB_KR2 + (size_t)4*NN*F2)                // must follow KR2
#define OB_ACT2    (OB_VR2 + (size_t)4*NN*F2)
#define OB_H2      (OB_ACT2 + (size_t)TT*NN*F2)
#define OB_TOTAL   (OB_H2 + (size_t)TT*NN*F2)

__device__ bf16 g_bf[OB_TOTAL];

// ---------------- fp32 scratch ----------------
__device__ float g_alpha[(size_t)4 * EE * NH];

// ---------------- CSR scratch ----------------
__device__ int g_deg[4 * NN];
__device__ int g_rowptr[4 * (NN + 1)];
__device__ int g_list[4 * EE];

// ---------------- asm helpers ----------------
__device__ __forceinline__ uint32_t smem_u32(const void* p) {
    return (uint32_t)__cvta_generic_to_shared(p);
}
__device__ __forceinline__ void cp16(uint32_t dst, const void* src, int sz) {
    asm volatile("cp.async.cg.shared.global [%0], [%1], 16, %2;" :: "r"(dst), "l"(src), "r"(sz));
}
__device__ __forceinline__ void cp_commit() { asm volatile("cp.async.commit_group;"); }
template<int N> __device__ __forceinline__ void cp_wait() {
    asm volatile("cp.async.wait_group %0;" :: "n"(N));
}
__device__ __forceinline__ void ldsm4(uint32_t& r0, uint32_t& r1, uint32_t& r2, uint32_t& r3, uint32_t a) {
    asm volatile("ldmatrix.sync.aligned.m8n8.x4.shared.b16 {%0,%1,%2,%3}, [%4];"
                 : "=r"(r0), "=r"(r1), "=r"(r2), "=r"(r3) : "r"(a));
}
__device__ __forceinline__ void ldsm4t(uint32_t& r0, uint32_t& r1, uint32_t& r2, uint32_t& r3, uint32_t a) {
    asm volatile("ldmatrix.sync.aligned.m8n8.x4.trans.shared.b16 {%0,%1,%2,%3}, [%4];"
                 : "=r"(r0), "=r"(r1), "=r"(r2), "=r"(r3) : "r"(a));
}
__device__ __forceinline__ void mma_bf16(float* c, const uint32_t* a, const uint32_t* b) {
    asm volatile("mma.sync.aligned.m16n8k16.row.col.f32.bf16.bf16.f32 "
                 "{%0,%1,%2,%3}, {%4,%5,%6,%7}, {%8,%9}, {%0,%1,%2,%3};"
                 : "+f"(c[0]), "+f"(c[1]), "+f"(c[2]), "+f"(c[3])
                 : "r"(a[0]), "r"(a[1]), "r"(a[2]), "r"(a[3]), "r"(b[0]), "r"(b[1]));
}

// ---------------- fused conversion: x -> XB AND pack Wk|Wq|Wv -> WKQV1 ----------------
__global__ void fused_cvt1(const float* __restrict__ x, bf16* __restrict__ XB,
                           const float* __restrict__ Wk, const float* __restrict__ Wq,
                           const float* __restrict__ Wv, bf16* __restrict__ WP)
{
    const size_t n4x = (size_t)TT * NN * F0 / 4;
    const size_t n4w = (size_t)TT * F0 * 3 * F1 / 4;
    size_t stride = (size_t)gridDim.x * blockDim.x;
    for (size_t i = (size_t)blockIdx.x * blockDim.x + threadIdx.x; i < n4x + n4w; i += stride) {
        float4 v;
        bf16* outp;
        if (i < n4x) {
            v = ((const float4*)x)[i];
            outp = XB + i * 4;
        } else {
            size_t idx = (i - n4x) * 4;
            int j = (int)(idx % (size_t)(3 * F1));
            size_t tk = idx / (size_t)(3 * F1);
            int m = j / F1, c = j % F1;
            const float* W = (m == 0) ? Wk : ((m == 1) ? Wq : Wv);
            v = *(const float4*)(W + tk * F1 + c);
            outp = WP + idx;
        }
        bf162 a, b;
        a.x = __float2bfloat16(v.x); a.y = __float2bfloat16(v.y);
        b.x = __float2bfloat16(v.z); b.y = __float2bfloat16(v.w);
        ((bf162*)outp)[0] = a;
        ((bf162*)outp)[1] = b;
    }
}

__global__ void cvt_bf4(const float* __restrict__ in, bf16* __restrict__ out, size_t n4) {
    size_t stride = (size_t)gridDim.x * blockDim.x;
    for (size_t i = (size_t)blockIdx.x * blockDim.x + threadIdx.x; i < n4; i += stride) {
        float4 v = ((const float4*)in)[i];
        bf162 a, b;
        a.x = __float2bfloat16(v.x); a.y = __float2bfloat16(v.y);
        b.x = __float2bfloat16(v.z); b.y = __float2bfloat16(v.w);
        ((bf162*)out)[i * 2] = a;
        ((bf162*)out)[i * 2 + 1] = b;
    }
}

__global__ void pack3w(const float* __restrict__ Wk, const float* __restrict__ Wq,
                       const float* __restrict__ Wv, bf16* __restrict__ out, int Kd, int Fo) {
    size_t total4 = (size_t)TT * Kd * 3 * Fo / 4;
    size_t stride = (size_t)gridDim.x * blockDim.x;
    for (size_t i = (size_t)blockIdx.x * blockDim.x + threadIdx.x; i < total4; i += stride) {
        size_t idx = i * 4;
        int j = (int)(idx % (size_t)(3 * Fo));
        size_t tk = idx / (size_t)(3 * Fo);
        int m = j / Fo, c = j % Fo;
        const float* W = (m == 0) ? Wk : ((m == 1) ? Wq : Wv);
        float4 v = *(const float4*)(W + tk * Fo + c);
        bf162 a, b;
        a.x = __float2bfloat16(v.x); a.y = __float2bfloat16(v.y);
        b.x = __float2bfloat16(v.z); b.y = __float2bfloat16(v.w);
        bf162* o = (bf162*)(out + idx);
        o[0] = a; o[1] = b;
    }
}

// pack rel weights: BP[mat][st][h][k][idx*D + n] = REL[mat][2*st+idx][h][k][n]
__global__ void packrel(const float* __restrict__ arel, const float* __restrict__ mrel,
                        bf16* __restrict__ BP, int D)
{
    size_t total4 = (size_t)2 * 2 * 8 * D * 2 * D / 4;
    size_t stride = (size_t)gridDim.x * blockDim.x;
    for (size_t i = (size_t)blockIdx.x * blockDim.x + threadIdx.x; i < total4; i += stride) {
        size_t idx = i * 4;
        int twoD = 2 * D;
        int n2 = (int)(idx % (size_t)twoD);
        size_t r = idx / (size_t)twoD;
        int k = (int)(r % D); r /= D;
        int h = (int)(r % 8); r /= 8;
        int st = (int)(r % 2);
        int mat = (int)(r / 2);
        int half = n2 / D, n = n2 % D;
        int e = st * 2 + half;
        const float* R = (mat == 0 ? arel : mrel) + (((size_t)e * 8 + h) * D + k) * D + n;
        float4 v = *(const float4*)R;
        bf162 a, b;
        a.x = __float2bfloat16(v.x); a.y = __float2bfloat16(v.y);
        b.x = __float2bfloat16(v.z); b.y = __float2bfloat16(v.w);
        bf162* o = (bf162*)(BP + idx);
        o[0] = a; o[1] = b;
    }
}

// ---------------- CSR build kernels ----------------
__global__ void zero_int(int* p, int n) {
    int i = blockIdx.x * blockDim.x + threadIdx.x;
    if (i < n) p[i] = 0;
}

__global__ void hist_edges(const int* __restrict__ d0, const int* __restrict__ d1,
                           const int* __restrict__ d2, const int* __restrict__ d3,
                           int* __restrict__ deg4)
{
    int idx = blockIdx.x * blockDim.x + threadIdx.x;
    if (idx >= 4 * EE) return;
    int t = idx / EE, e = idx % EE;
    int dn = (t == 0 ? d0 : (t == 1 ? d1 : (t == 2 ? d2 : d3)))[e];
    atomicAdd(&deg4[t * NN + dn], 1);
}

__global__ void scan_deg(int* __restrict__ deg4, int* __restrict__ rowptr4)
{
    int t = blockIdx.x;
    int* deg = deg4 + t * NN;
    int* rp = rowptr4 + t * (NN + 1);
    __shared__ int sums[256];
    int tid = threadIdx.x;
    const int CH = (NN + 255) / 256;
    int base = tid * CH;
    int s = 0;
    for (int i = 0; i < CH; i++) {
        int idx = base + i;
        if (idx < NN) s += deg[idx];
    }
    sums[tid] = s;
    __syncthreads();
    for (int off = 1; off < 256; off <<= 1) {
        int v = (tid >= off) ? sums[tid - off] : 0;
        __syncthreads();
        if (tid >= off) sums[tid] += v;
        __syncthreads();
    }
    int run = (tid == 0) ? 0 : sums[tid - 1];
    for (int i = 0; i < CH; i++) {
        int idx = base + i;
        if (idx < NN) {
            int d = deg[idx];
            rp[idx] = run;
            deg[idx] = run;
            run += d;
        }
    }
    if (tid == 255) rp[NN] = sums[255];
}

__global__ void scatter_edges(const int* __restrict__ d0, const int* __restrict__ d1,
                              const int* __restrict__ d2, const int* __restrict__ d3,
                              int* __restrict__ cursor4, int* __restrict__ list4)
{
    int idx = blockIdx.x * blockDim.x + threadIdx.x;
    if (idx >= 4 * EE) return;
    int t = idx / EE, e = idx % EE;
    int dn = (t == 0 ? d0 : (t == 1 ? d1 : (t == 2 ? d2 : d3)))[e];
    int pos = atomicAdd(&cursor4[t * NN + dn], 1);
    list4[t * EE + pos] = e;
}

// ---------------- BIG bf16 GEMM: 128x128x32, 4 warps (64x64), 4-stage, 2 CTA/SM ----
// bias: 3-way select (bk|bq|bv) by column block of size Fo; bias value = bp[z*Fo + col%Fo].
#define G2STAGES 4
#define G2SMEM_BYTES (G2STAGES * (128 * 40 + 32 * 136) * 2)

__global__ __launch_bounds__(128, 2)
void gemm_bf2(const bf16* __restrict__ A, const bf16* __restrict__ B,
              const float* __restrict__ bk, const float* __restrict__ bq,
              const float* __restrict__ bv, int Fo,
              bf16* __restrict__ C, int M, int Nn, int K,
              size_t sA, size_t sB, size_t sC)
{
    extern __shared__ char dynsmem[];
    bf16 (*As)[128][40] = (bf16(*)[128][40])dynsmem;
    bf16 (*Bs)[32][136] = (bf16(*)[32][136])(dynsmem + G2STAGES * 128 * 40 * 2);

    int z = blockIdx.z;
    A += (size_t)z * sA;
    B += (size_t)z * sB;
    C += (size_t)z * sC;

    int bm = blockIdx.y * 128, bn = blockIdx.x * 128;
    int tid = threadIdx.x;
    int lane = tid & 31;
    int w = tid >> 5;
    int wm = (w & 1) * 64;
    int wn = (w >> 1) * 64;
    int tg = lane & 3;
    int rowg = lane >> 2;

    float acc[4][8][4];
#pragma unroll
    for (int i = 0; i < 4; i++)
#pragma unroll
        for (int j = 0; j < 8; j++)
#pragma unroll
            for (int r = 0; r < 4; r++) acc[i][j][r] = 0.f;

    const int nk = K / 32;

#define G2LOAD(kt, s)                                                                  \
    do {                                                                               \
        _Pragma("unroll")                                                              \
        for (int p = 0; p < 4; p++) {                                                  \
            int idx = tid + p * 128;                                                   \
            int m = idx >> 2, c = (idx & 3) * 8;                                       \
            int gm = bm + m;                                                           \
            const bf16* sp = A + (size_t)(gm < M ? gm : 0) * K + (kt) + c;             \
            cp16(smem_u32(&As[s][m][c]), sp, gm < M ? 16 : 0);                         \
        }                                                                              \
        _Pragma("unroll")                                                              \
        for (int p = 0; p < 4; p++) {                                                  \
            int idx = tid + p * 128;                                                   \
            int kr = idx >> 4, c = (idx & 15) * 8;                                     \
            const bf16* sp = B + (size_t)((kt) + kr) * Nn + bn + c;                    \
            cp16(smem_u32(&Bs[s][kr][c]), sp, 16);                                     \
        }                                                                              \
    } while (0)

#pragma unroll
    for (int s = 0; s < G2STAGES - 1; s++) {
        if (s < nk) G2LOAD(s * 32, s);
        cp_commit();
    }

    for (int it = 0; it < nk; it++) {
        cp_wait<G2STAGES - 2>();
        __syncthreads();
        int nxt = it + G2STAGES - 1;
        if (nxt < nk) G2LOAD(nxt * 32, nxt % G2STAGES);
        cp_commit();

        int cur = it % G2STAGES;
#pragma unroll
        for (int ks = 0; ks < 2; ks++) {
            int k0 = ks * 16;
            uint32_t af[4][4], bfr[8][2];
#pragma unroll
            for (int mt = 0; mt < 4; mt++) {
                int row = wm + mt * 16 + (lane & 15);
                int coff = k0 + ((lane >> 4) << 3);
                ldsm4(af[mt][0], af[mt][1], af[mt][2], af[mt][3],
                      smem_u32(&As[cur][row][coff]));
            }
#pragma unroll
            for (int ntp = 0; ntp < 4; ntp++) {
                int row = k0 + (lane & 7) + ((lane >> 3) & 1) * 8;
                int col = wn + ntp * 16 + ((lane >> 4) << 3);
                uint32_t r0, r1, r2, r3;
                ldsm4t(r0, r1, r2, r3, smem_u32(&Bs[cur][row][col]));
                bfr[ntp * 2][0] = r0; bfr[ntp * 2][1] = r1;
                bfr[ntp * 2 + 1][0] = r2; bfr[ntp * 2 + 1][1] = r3;
            }
#pragma unroll
            for (int mt = 0; mt < 4; mt++)
#pragma unroll
                for (int nt = 0; nt < 8; nt++)
                    mma_bf16(acc[mt][nt], af[mt], bfr[nt]);
        }
    }
#undef G2LOAD

#pragma unroll
    for (int mt = 0; mt < 4; mt++) {
#pragma unroll
        for (int nt = 0; nt < 8; nt++) {
            int gm0 = bm + wm + mt * 16 + rowg;
            int gn0 = bn + wn + nt * 8 + tg * 2;
            int m = gn0 / Fo, c = gn0 - m * Fo;       // pair never straddles Fo (even cols)
            const float* bp = (m == 0) ? bk : ((m == 1) ? bq : bv);
            float b0 = bp[z * Fo + c], b1 = bp[z * Fo + c + 1];
            if (gm0 < M) {
                bf162 v;
                v.x = __float2bfloat16(acc[mt][nt][0] + b0);
                v.y = __float2bfloat16(acc[mt][nt][1] + b1);
                *(bf162*)(C + (size_t)gm0 * Nn + gn0) = v;
            }
            if (gm0 + 8 < M) {
                bf162 v;
                v.x = __float2bfloat16(acc[mt][nt][2] + b0);
                v.y = __float2bfloat16(acc[mt][nt][3] + b1);
                *(bf162*)(C + (size_t)(gm0 + 8) * Nn + gn0) = v;
            }
        }
    }
}

// ---------------- 128x128 bf16 GEMM (paired rel transforms), 4-stage, 256 thr --------
#define GSTAGES 4
#define GSMEM_BYTES (GSTAGES * (128 * 40 + 32 * 136) * 2)

__global__ __launch_bounds__(256, 2)
void gemm_bf(const bf16* __restrict__ A, const bf16* __restrict__ B,
             const float* __restrict__ bias, bf16* __restrict__ C,
             int M, int Nn, int K, int lda, int ldb, int ldc,
             size_t sA, size_t sA2, size_t sB, size_t sB2,
             size_t sBias, size_t sC, size_t sC2)
{
    extern __shared__ char dynsmem[];
    bf16 (*As)[128][40] = (bf16(*)[128][40])dynsmem;
    bf16 (*Bs)[32][136] = (bf16(*)[32][136])(dynsmem + GSTAGES * 128 * 40 * 2);

    int z = blockIdx.z;
    int zl = z & 7, zh = z >> 3;
    A += (size_t)zl * sA + (size_t)zh * sA2;
    B += (size_t)zl * sB + (size_t)zh * sB2;
    C += (size_t)zl * sC + (size_t)zh * sC2;
    if (bias) bias += (size_t)zl * sBias;

    int bm = blockIdx.y * 128, bn = blockIdx.x * 128;
    int tid = threadIdx.x;
    int lane = tid & 31;
    int w = tid >> 5;
    int wm = (w & 1) * 64;
    int wn = (w >> 1) * 32;
    int tg = lane & 3;
    int rowg = lane >> 2;

    float acc[4][4][4];
#pragma unroll
    for (int i = 0; i < 4; i++)
#pragma unroll
        for (int j = 0; j < 4; j++)
#pragma unroll
            for (int r = 0; r < 4; r++) acc[i][j][r] = 0.f;

    const int nk = K / 32;

#define GLOAD(kt, s)                                                                   \
    do {                                                                               \
        _Pragma("unroll")                                                              \
        for (int p = 0; p < 2; p++) {                                                  \
            int idx = tid + p * 256;                                                   \
            int m = idx >> 2, c = (idx & 3) * 8;                                       \
            int gm = bm + m;                                                           \
            const bf16* sp = A + (size_t)(gm < M ? gm : 0) * lda + (kt) + c;           \
            cp16(smem_u32(&As[s][m][c]), sp, gm < M ? 16 : 0);                         \
        }                                                                              \
        _Pragma("unroll")                                                              \
        for (int p = 0; p < 2; p++) {                                                  \
            int idx = tid + p * 256;                                                   \
            int kr = idx >> 4, c = (idx & 15) * 8;                                     \
            int gn = bn + c;                                                           \
            const bf16* sp = B + (size_t)((kt) + kr) * ldb + (gn < Nn ? gn : 0);       \
            cp16(smem_u32(&Bs[s][kr][c]), sp, gn < Nn ? 16 : 0);                       \
        }                                                                              \
    } while (0)

#pragma unroll
    for (int s = 0; s < GSTAGES - 1; s++) {
        if (s < nk) GLOAD(s * 32, s);
        cp_commit();
    }

    for (int it = 0; it < nk; it++) {
        cp_wait<GSTAGES - 2>();
        __syncthreads();
        int nxt = it + GSTAGES - 1;
        int slot = nxt % GSTAGES;
        if (nxt < nk) GLOAD(nxt * 32, slot);
        cp_commit();

        int cur = it % GSTAGES;
#pragma unroll
        for (int ks = 0; ks < 2; ks++) {
            int k0 = ks * 16;
            uint32_t af[4][4], bfr[4][2];
#pragma unroll
            for (int mt = 0; mt < 4; mt++) {
                int row = wm + mt * 16 + (lane & 15);
                int coff = k0 + ((lane >> 4) << 3);
                ldsm4(af[mt][0], af[mt][1], af[mt][2], af[mt][3],
                      smem_u32(&As[cur][row][coff]));
            }
#pragma unroll
            for (int ntp = 0; ntp < 2; ntp++) {
                int row = k0 + (lane & 7) + ((lane >> 3) & 1) * 8;
                int col = wn + ntp * 16 + ((lane >> 4) << 3);
                uint32_t r0, r1, r2, r3;
                ldsm4t(r0, r1, r2, r3, smem_u32(&Bs[cur][row][col]));
                bfr[ntp * 2][0] = r0; bfr[ntp * 2][1] = r1;
                bfr[ntp * 2 + 1][0] = r2; bfr[ntp * 2 + 1][1] = r3;
            }
#pragma unroll
            for (int mt = 0; mt < 4; mt++)
#pragma unroll
                for (int nt = 0; nt < 4; nt++)
                    mma_bf16(acc[mt][nt], af[mt], bfr[nt]);
        }
    }
#undef GLOAD

#pragma unroll
    for (int mt = 0; mt < 4; mt++) {
#pragma unroll
        for (int nt = 0; nt < 4; nt++) {
            int gm0 = bm + wm + mt * 16 + rowg;
            int gn0 = bn + wn + nt * 8 + tg * 2;
            if (gn0 >= Nn) continue;
            float b0 = 0.f, b1 = 0.f;
            if (bias) { b0 = bias[gn0]; b1 = bias[gn0 + 1]; }
            if (gm0 < M) {
                bf162 v;
                v.x = __float2bfloat16(acc[mt][nt][0] + b0);
                v.y = __float2bfloat16(acc[mt][nt][1] + b1);
                *(bf162*)(C + (size_t)gm0 * ldc + gn0) = v;
            }
            if (gm0 + 8 < M) {
                bf162 v;
                v.x = __float2bfloat16(acc[mt][nt][2] + b0);
                v.y = __float2bfloat16(acc[mt][nt][3] + b1);
                *(bf162*)(C + (size_t)(gm0 + 8) * ldc + gn0) = v;
            }
        }
    }
}

// ---------------- edge logits: ALL 4 edge types in one launch ----------------
__device__ __forceinline__ float dot8(uint4 a, uint4 b) {
    const bf162* pa = (const bf162*)&a;
    const bf162* pb = (const bf162*)&b;
    float s = 0.f;
#pragma unroll
    for (int i = 0; i < 4; i++) {
        float2 fa = __bfloat1622float2(pa[i]);
        float2 fb = __bfloat1622float2(pb[i]);
        s = fmaf(fa.x, fb.x, s);
        s = fmaf(fa.y, fb.y, s);
    }
    return s;
}

// warp per edge, all 8 heads; blockIdx.y = edge type.
// q = kqv[dt] Q section (head stride D); kr = paired KR[st] + idx*D (head stride 2D).
template<int D, int F>
__global__ void edge_logits_all(const bf16* __restrict__ kqv, const bf16* __restrict__ krbase,
                                const int* __restrict__ e0p, const int* __restrict__ e1p,
                                const int* __restrict__ e2p, const int* __restrict__ e3p,
                                const float* __restrict__ prel, float* __restrict__ alpha,
                                float scale)
{
    constexpr int VEC = D / 4;
    constexpr int NV = VEC / 8;
    int et = blockIdx.y;
    int e = (blockIdx.x * blockDim.x + threadIdx.x) >> 5;
    int lane = threadIdx.x & 31;
    if (e >= EE) return;
    const int* ei = (et == 0) ? e0p : ((et == 1) ? e1p : ((et == 2) ? e2p : e3p));
    int dt = et & 1, st = et >> 1;
    int sN = ei[e], dN = ei[EE + e];
    int h = lane >> 2, sub = lane & 3;

    const bf16* q = kqv + (size_t)dt * NN * 3 * F + F;
    const bf16* kr = krbase + (size_t)st * NN * 2 * F + (size_t)(et & 1) * D;
    const uint4* qp = (const uint4*)(q + (size_t)dN * 3 * F + h * D + sub * VEC);
    const uint4* kp = (const uint4*)(kr + (size_t)sN * 2 * F + h * 2 * D + sub * VEC);

    float acc = 0.f;
#pragma unroll
    for (int i = 0; i < NV; i++) acc += dot8(qp[i], kp[i]);
    acc += __shfl_xor_sync(0xFFFFFFFFu, acc, 1);
    acc += __shfl_xor_sync(0xFFFFFFFFu, acc, 2);

    if (sub == 0)
        alpha[((size_t)et * EE + e) * NH + h] = expf(acc * prel[et * NH + h] * scale);
}

// ---------------- CSR gather: warp per (dst node, head), two edge types -------------
template<int D>
__global__ void edge_gather(const bf16* __restrict__ vrA, const bf16* __restrict__ vrB,
                            int ldv, int hsv,
                            const float* __restrict__ alA, const float* __restrict__ alB,
                            const int* __restrict__ srcA, const int* __restrict__ srcB,
                            const int* __restrict__ rpA, const int* __restrict__ listA,
                            const int* __restrict__ rpB, const int* __restrict__ listB,
                            bf16* __restrict__ outp, int F)
{
    constexpr int PL = D / 32;
    int w = (blockIdx.x * blockDim.x + threadIdx.x) >> 5;
    int lane = threadIdx.x & 31;
    if (w >= NN * NH) return;
    int node = w / NH, h = w % NH;
    size_t loff = (size_t)h * hsv + lane * PL;

    float accA[PL], accB[PL];
#pragma unroll
    for (int j = 0; j < PL; j++) { accA[j] = 0.f; accB[j] = 0.f; }
    float sA = 0.f, sB = 0.f;

    int bA = rpA[node], eA = rpA[node + 1];
    for (int i = bA; i < eA; i++) {
        int e = listA[i];
        float ex = alA[(size_t)e * NH + h];
        int s = srcA[e];
        const bf16* vp = vrA + (size_t)s * ldv + loff;
        if (PL == 4) {
            uint2 u = *(const uint2*)vp;
            float2 f0 = __bfloat1622float2(*(const bf162*)&u.x);
            float2 f1 = __bfloat1622float2(*(const bf162*)&u.y);
            accA[0] = fmaf(ex, f0.x, accA[0]);
            accA[1] = fmaf(ex, f0.y, accA[1]);
            accA[2] = fmaf(ex, f1.x, accA[2]);
            accA[3] = fmaf(ex, f1.y, accA[3]);
        } else {
            uint32_t u = *(const uint32_t*)vp;
            float2 f = __bfloat1622float2(*(const bf162*)&u);
            accA[0] = fmaf(ex, f.x, accA[0]);
            accA[1] = fmaf(ex, f.y, accA[1]);
        }
        sA += ex;
    }

    int bB = rpB[node], eB = rpB[node + 1];
    for (int i = bB; i < eB; i++) {
        int e = listB[i];
        float ex = alB[(size_t)e * NH + h];
        int s = srcB[e];
        const bf16* vp = vrB + (size_t)s * ldv + loff;
        if (PL == 4) {
            uint2 u = *(const uint2*)vp;
            float2 f0 = __bfloat1622float2(*(const bf162*)&u.x);
            float2 f1 = __bfloat1622float2(*(const bf162*)&u.y);
            accB[0] = fmaf(ex, f0.x, accB[0]);
            accB[1] = fmaf(ex, f0.y, accB[1]);
            accB[2] = fmaf(ex, f1.x, accB[2]);
            accB[3] = fmaf(ex, f1.y, accB[3]);
        } else {
            uint32_t u = *(const uint32_t*)vp;
            float2 f = __bfloat1622float2(*(const bf162*)&u);
            accB[0] = fmaf(ex, f.x, accB[0]);
            accB[1] = fmaf(ex, f.y, accB[1]);
        }
        sB += ex;
    }

    float invA = 1.f / (sA + 1e-16f);
    float invB = 1.f / (sB + 1e-16f);
    bf16* op = outp + (size_t)node * F + (size_t)h * D + lane * PL;
#pragma unroll
    for (int j = 0; j < PL; j += 2) {
        float x0 = accA[j] * invA + accB[j] * invB;
        float x1 = accA[j + 1] * invA + accB[j + 1] * invB;
        bf162 r;
        r.x = __float2bfloat16(0.5f * x0 * (1.0f + erff(x0 * 0.70710678f)));
        r.y = __float2bfloat16(0.5f * x1 * (1.0f + erff(x1 * 0.70710678f)));
        *(bf162*)(op + j) = r;
    }
}

// ---------------- final linear + row softmax ----------------
__global__ void final_kernel(const bf16* __restrict__ h2, const float* __restrict__ W,
                             const float* __restrict__ b, float* __restrict__ out)
{
    int warp = (blockIdx.x * blockDim.x + threadIdx.x) >> 5;
    int lane = threadIdx.x & 31;
    if (warp >= TT * NN) return;
    const bf16* hp = h2 + (size_t)warp * F2;
    float acc[OUTF];
#pragma unroll
    for (int o = 0; o < OUTF; o++) acc[o] = 0.f;
    for (int f = lane; f < F2; f += 32) {
        float xv = __bfloat162float(hp[f]);
        const float* wp = W + (size_t)f * OUTF;
#pragma unroll
        for (int o = 0; o < OUTF; o++) acc[o] = fmaf(xv, wp[o], acc[o]);
    }
#pragma unroll
    for (int o = 0; o < OUTF; o++) {
#pragma unroll
        for (int off = 16; off; off >>= 1) acc[o] += __shfl_down_sync(0xFFFFFFFFu, acc[o], off);
    }
    if (lane == 0) {
        float l[OUTF];
        float m = -1e30f;
#pragma unroll
        for (int o = 0; o < OUTF; o++) { l[o] = acc[o] + b[o]; m = fmaxf(m, l[o]); }
        float s = 0.f;
#pragma unroll
        for (int o = 0; o < OUTF; o++) { l[o] = expf(l[o] - m); s += l[o]; }
        float inv = 1.f / s;
        float* op = out + (size_t)warp * OUTF;
#pragma unroll
        for (int o = 0; o < OUTF; o++) op[o] = l[o] * inv;
    }
}

// ---------------- host helpers ----------------
static void gemm_big(const bf16* A, const bf16* B, bf16* C, int M, int N, int K,
                     size_t sA, size_t sB, size_t sC,
                     const float* bk, const float* bq, const float* bv, int Fo)
{
    dim3 grid(N / 128, (M + 127) / 128, TT);
    gemm_bf2<<<grid, 128, G2SMEM_BYTES>>>(A, B, bk, bq, bv, Fo, C, M, N, K, sA, sB, sC);
}

// paired rel: one launch per (layer, st): z = mat*8 + h; C = KR[st] (K), +vroff (V)
static void gemm_relp(const bf16* Abase, const bf16* BPst, bf16* Cbase,
                      int D, int F, size_t vroff)
{
    dim3 grid((2 * D + 127) / 128, (NN + 127) / 128, 16);
    gemm_bf<<<grid, 256, GSMEM_BYTES>>>(Abase, BPst, nullptr, Cbase,
        NN, 2 * D, D, 3 * F, 2 * D, 2 * F,
        (size_t)D, (size_t)2 * F,
        (size_t)D * 2 * D, (size_t)8 * D * 2 * D,
        0, (size_t)2 * D, vroff);
}

extern "C" void kernel_launch(void* const* d_in, const int* in_sizes, int n_in,
                              void* d_out, int out_size)
{
    (void)in_sizes; (void)n_in; (void)out_size;
    const float* x     = (const float*)d_in[0];
    const int* ei[4]   = {(const int*)d_in[1], (const int*)d_in[2],
                          (const int*)d_in[3], (const int*)d_in[4]};
    const float* Wk1 = (const float*)d_in[5];  const float* bk1 = (const float*)d_in[6];
    const float* Wq1 = (const float*)d_in[7];  const float* bq1 = (const float*)d_in[8];
    const float* Wv1 = (const float*)d_in[9];  const float* bv1 = (const float*)d_in[10];
    const float* Wa1 = (const float*)d_in[11]; const float* ba1 = (const float*)d_in[12];
    const float* arel1 = (const float*)d_in[13];
    const float* mrel1 = (const float*)d_in[14];
    const float* prel1 = (const float*)d_in[15];
    const float* Wk2 = (const float*)d_in[16]; const float* bk2 = (const float*)d_in[17];
    const float* Wq2 = (const float*)d_in[18]; const float* bq2 = (const float*)d_in[19];
    const float* Wv2 = (const float*)d_in[20]; const float* bv2 = (const float*)d_in[21];
    const float* Wa2 = (const float*)d_in[22]; const float* ba2 = (const float*)d_in[23];
    const float* arel2 = (const float*)d_in[24];
    const float* mrel2 = (const float*)d_in[25];
    const float* prel2 = (const float*)d_in[26];
    const float* Wlin = (const float*)d_in[27]; const float* blin = (const float*)d_in[28];
    float* out = (float*)d_out;

    cudaFuncSetAttribute(gemm_bf, cudaFuncAttributeMaxDynamicSharedMemorySize, GSMEM_BYTES);
    cudaFuncSetAttribute(gemm_bf2, cudaFuncAttributeMaxDynamicSharedMemorySize, G2SMEM_BYTES);

    bf16* BB = nullptr;
    float* ALPHA = nullptr;
    int* DEG = nullptr; int* RP = nullptr; int* LST = nullptr;
    cudaGetSymbolAddress((void**)&BB, g_bf);
    cudaGetSymbolAddress((void**)&ALPHA, g_alpha);
    cudaGetSymbolAddress((void**)&DEG, g_deg);
    cudaGetSymbolAddress((void**)&RP, g_rowptr);
    cudaGetSymbolAddress((void**)&LST, g_list);

    bf16* XB = BB + OB_XB;
    bf16* WKQV1 = BB + OB_WKQV1; bf16* WA1B = BB + OB_WA1; bf16* BP1 = BB + OB_BP1;
    bf16* WKQV2 = BB + OB_WKQV2; bf16* WA2B = BB + OB_WA2; bf16* BP2 = BB + OB_BP2;
    bf16* KQV1 = BB + OB_KQV1; bf16* KR1 = BB + OB_KR1;
    bf16* ACT1 = BB + OB_ACT1; bf16* H1 = BB + OB_H1;
    bf16* KQV2 = BB + OB_KQV2; bf16* KR2 = BB + OB_KR2;
    bf16* ACT2 = BB + OB_ACT2; bf16* H2 = BB + OB_H2;
    bf16* VR1 = BB + OB_VR1;   // = KR1 + 4*NN*F1 (mat offset)
    bf16* VR2 = BB + OB_VR2;

    const int elb = (EE * 32 + 255) / 256;
    const int ggb = (NN * NH * 32 + 255) / 256;
    const int ceb = (4 * EE + 255) / 256;
    const int* dp[4] = {ei[0] + EE, ei[1] + EE, ei[2] + EE, ei[3] + EE};
    const size_t vroff1 = (size_t)OB_VR1 - OB_KR1;
    const size_t vroff2 = (size_t)OB_VR2 - OB_KR2;

    // ---- launches 1-3; #4 = rel GEMM (profiled) ----
    fused_cvt1<<<3072, 256>>>(x, XB, Wk1, Wq1, Wv1, WKQV1);                     // 1
    packrel<<<1024, 256>>>(arel1, mrel1, BP1, D1);                              // 2
    gemm_big(XB, WKQV1, KQV1, NN, 3 * F1, F0,                                   // 3
             (size_t)NN * F0, (size_t)F0 * 3 * F1, (size_t)NN * 3 * F1,
             bk1, bq1, bv1, F1);
    gemm_relp(KQV1, BP1, KR1, D1, F1, vroff1);                                  // 4 (profiled, st=0)
    gemm_relp(KQV1 + (size_t)NN * 3 * F1, BP1 + (size_t)8 * D1 * 2 * D1,        // 5 (st=1)
              KR1 + (size_t)NN * 2 * F1, D1, F1, vroff1);

    // CSR build (shared by both layers)
    zero_int<<<(4 * NN + 255) / 256, 256>>>(DEG, 4 * NN);
    hist_edges<<<ceb, 256>>>(dp[0], dp[1], dp[2], dp[3], DEG);
    scan_deg<<<4, 256>>>(DEG, RP);
    scatter_edges<<<ceb, 256>>>(dp[0], dp[1], dp[2], dp[3], DEG, LST);

    // remaining conversions
    packrel<<<256, 256>>>(arel2, mrel2, BP2, D2);
    cvt_bf4<<<512, 256>>>(Wa1, WA1B, (size_t)TT * F1 * F1 / 4);
    pack3w<<<1024, 256>>>(Wk2, Wq2, Wv2, WKQV2, F1, F2);
    cvt_bf4<<<512, 256>>>(Wa2, WA2B, (size_t)TT * F2 * F2 / 4);

    // ---- layer 1 edge phase ----
    {
        float scale = 1.f / sqrtf((float)D1);
        dim3 g(elb, 4);
        edge_logits_all<D1, F1><<<g, 256>>>(KQV1, KR1, ei[0], ei[1], ei[2], ei[3],
                                            prel1, ALPHA, scale);
    }
    // dst0 <- e0 (st0,idx0), e2 (st1,idx0);  dst1 <- e1 (st0,idx1), e3 (st1,idx1)
    edge_gather<D1><<<ggb, 256>>>(VR1, VR1 + (size_t)NN * 2 * F1, 2 * F1, 2 * D1,
        ALPHA, ALPHA + (size_t)2 * EE * NH, ei[0], ei[2],
        RP, LST, RP + 2 * (NN + 1), LST + 2 * EE, ACT1, F1);
    edge_gather<D1><<<ggb, 256>>>(VR1 + D1, VR1 + (size_t)NN * 2 * F1 + D1, 2 * F1, 2 * D1,
        ALPHA + (size_t)1 * EE * NH, ALPHA + (size_t)3 * EE * NH, ei[1], ei[3],
        RP + 1 * (NN + 1), LST + 1 * EE, RP + 3 * (NN + 1), LST + 3 * EE,
        ACT1 + (size_t)NN * F1, F1);

    gemm_big(ACT1, WA1B, H1, NN, F1, F1,
             (size_t)NN * F1, (size_t)F1 * F1, (size_t)NN * F1, ba1, ba1, ba1, F1);

    // ============ LAYER 2 ============
    gemm_big(H1, WKQV2, KQV2, NN, 3 * F2, F1,
             (size_t)NN * F1, (size_t)F1 * 3 * F2, (size_t)NN * 3 * F2, bk2, bq2, bv2, F2);

    gemm_relp(KQV2, BP2, KR2, D2, F2, vroff2);
    gemm_relp(KQV2 + (size_t)NN * 3 * F2, BP2 + (size_t)8 * D2 * 2 * D2,
              KR2 + (size_t)NN * 2 * F2, D2, F2, vroff2);

    {
        float scale = 1.f / sqrtf((float)D2);
        dim3 g(elb, 4);
        edge_logits_all<D2, F2><<<g, 256>>>(KQV2, KR2, ei[0], ei[1], ei[2], ei[3],
                                            prel2, ALPHA, scale);
    }
    edge_gather<D2><<<ggb, 256>>>(VR2, VR2 + (size_t)NN * 2 * F2, 2 * F2, 2 * D2,
        ALPHA, ALPHA + (size_t)2 * EE * NH, ei[0], ei[2],
        RP, LST, RP + 2 * (NN + 1), LST + 2 * EE, ACT2, F2);
    edge_gather<D2><<<ggb, 256>>>(VR2 + D2, VR2 + (size_t)NN * 2 * F2 + D2, 2 * F2, 2 * D2,
        ALPHA + (size_t)1 * EE * NH, ALPHA + (size_t)3 * EE * NH, ei[1], ei[3],
        RP + 1 * (NN + 1), LST + 1 * EE, RP + 3 * (NN + 1), LST + 3 * EE,
        ACT2 + (size_t)NN * F2, F2);

    gemm_big(ACT2, WA2B, H2, NN, F2, F2,
             (size_t)NN * F2, (size_t)F2 * F2, (size_t)NN * F2, ba2, ba2, ba2, F2);

    // ============ final ============
    final_kernel<<<(TT * NN * 32 + 255) / 256, 256>>>(H2, Wlin, blin, out);
}

// round 17
// speedup vs baseline: 1.3621x; 1.0012x over previous
#include <cuda_runtime.h>
#include <cuda_bf16.h>
#include <math.h>
#include <stdint.h>

// ---------------- problem constants ----------------
#define NN 10000
#define EE 60000
#define TT 2
#define NH 8
#define F0 2048
#define F1 1024
#define D1 128
#define F2 512
#define D2 64
#define OUTF 8

typedef __nv_bfloat16 bf16;
typedef __nv_bfloat162 bf162;

// ---------------- bf16 scratch offsets (elements) ----------------
// BP1/BP2: paired rel weights [mat(2)][st(2)][h(8)][D][2D]
// KR/VR:   paired layout [st(2)][NN][2F] (VR must follow KR at fixed offset)
#define OB_XB      ((size_t)0)
#define OB_WKQV1   (OB_XB + (size_t)TT*NN*F0)
#define OB_WA1     (OB_WKQV1 + (size_t)TT*F0*3*F1)
#define OB_BP1     (OB_WA1 + (size_t)TT*F1*F1)               // 2*2*8*D1*2*D1
#define OB_WKQV2   (OB_BP1 + (size_t)2*2*8*D1*2*D1)
#define OB_WA2     (OB_WKQV2 + (size_t)TT*F1*3*F2)
#define OB_BP2     (OB_WA2 + (size_t)TT*F2*F2)               // 2*2*8*D2*2*D2
#define OB_KQV1    (OB_BP2 + (size_t)2*2*8*D2*2*D2)
#define OB_KR1     (OB_KQV1 + (size_t)TT*NN*3*F1)            // 2*NN*2F1
#define OB_VR1     (OB_KR1 + (size_t)4*NN*F1)                // must follow KR1
#define OB_ACT1    (OB_VR1 + (size_t)4*NN*F1)
#define OB_H1      (OB_ACT1 + (size_t)TT*NN*F1)
#define OB_KQV2    (OB_H1 + (size_t)TT*NN*F1)
#define OB_KR2     (OB_KQV2 + (size_t)TT*NN*3*F2)
#define OB_VR2     (OB_KR2 + (size_t)4*NN*F2)                // must follow KR2
#define OB_ACT2    (OB_VR2 + (size_t)4*NN*F2)
#define OB_H2      (OB_ACT2 + (size_t)TT*NN*F2)
#define OB_TOTAL   (OB_H2 + (size_t)TT*NN*F2)

__device__ bf16 g_bf[OB_TOTAL];

// ---------------- fp32 scratch ----------------
__device__ float g_alpha[(size_t)4 * EE * NH];

// ---------------- CSR scratch ----------------
__device__ int g_deg[4 * NN];
__device__ int g_rowptr[4 * (NN + 1)];
__device__ int g_list[4 * EE];

// ---------------- asm helpers ----------------
__device__ __forceinline__ uint32_t smem_u32(const void* p) {
    return (uint32_t)__cvta_generic_to_shared(p);
}
__device__ __forceinline__ void cp16(uint32_t dst, const void* src, int sz) {
    asm volatile("cp.async.cg.shared.global [%0], [%1], 16, %2;" :: "r"(dst), "l"(src), "r"(sz));
}
__device__ __forceinline__ void cp_commit() { asm volatile("cp.async.commit_group;"); }
template<int N> __device__ __forceinline__ void cp_wait() {
    asm volatile("cp.async.wait_group %0;" :: "n"(N));
}
__device__ __forceinline__ void ldsm4(uint32_t& r0, uint32_t& r1, uint32_t& r2, uint32_t& r3, uint32_t a) {
    asm volatile("ldmatrix.sync.aligned.m8n8.x4.shared.b16 {%0,%1,%2,%3}, [%4];"
                 : "=r"(r0), "=r"(r1), "=r"(r2), "=r"(r3) : "r"(a));
}
__device__ __forceinline__ void ldsm4t(uint32_t& r0, uint32_t& r1, uint32_t& r2, uint32_t& r3, uint32_t a) {
    asm volatile("ldmatrix.sync.aligned.m8n8.x4.trans.shared.b16 {%0,%1,%2,%3}, [%4];"
                 : "=r"(r0), "=r"(r1), "=r"(r2), "=r"(r3) : "r"(a));
}
__device__ __forceinline__ void mma_bf16(float* c, const uint32_t* a, const uint32_t* b) {
    asm volatile("mma.sync.aligned.m16n8k16.row.col.f32.bf16.bf16.f32 "
                 "{%0,%1,%2,%3}, {%4,%5,%6,%7}, {%8,%9}, {%0,%1,%2,%3};"
                 : "+f"(c[0]), "+f"(c[1]), "+f"(c[2]), "+f"(c[3])
                 : "r"(a[0]), "r"(a[1]), "r"(a[2]), "r"(a[3]), "r"(b[0]), "r"(b[1]));
}

// ---------------- fused conversion: x -> XB AND pack Wk|Wq|Wv -> WKQV1 ----------------
__global__ void fused_cvt1(const float* __restrict__ x, bf16* __restrict__ XB,
                           const float* __restrict__ Wk, const float* __restrict__ Wq,
                           const float* __restrict__ Wv, bf16* __restrict__ WP)
{
    const size_t n4x = (size_t)TT * NN * F0 / 4;
    const size_t n4w = (size_t)TT * F0 * 3 * F1 / 4;
    size_t stride = (size_t)gridDim.x * blockDim.x;
    for (size_t i = (size_t)blockIdx.x * blockDim.x + threadIdx.x; i < n4x + n4w; i += stride) {
        float4 v;
        bf16* outp;
        if (i < n4x) {
            v = ((const float4*)x)[i];
            outp = XB + i * 4;
        } else {
            size_t idx = (i - n4x) * 4;
            int j = (int)(idx % (size_t)(3 * F1));
            size_t tk = idx / (size_t)(3 * F1);
            int m = j / F1, c = j % F1;
            const float* W = (m == 0) ? Wk : ((m == 1) ? Wq : Wv);
            v = *(const float4*)(W + tk * F1 + c);
            outp = WP + idx;
        }
        bf162 a, b;
        a.x = __float2bfloat16(v.x); a.y = __float2bfloat16(v.y);
        b.x = __float2bfloat16(v.z); b.y = __float2bfloat16(v.w);
        ((bf162*)outp)[0] = a;
        ((bf162*)outp)[1] = b;
    }
}

__global__ void cvt_bf4(const float* __restrict__ in, bf16* __restrict__ out, size_t n4) {
    size_t stride = (size_t)gridDim.x * blockDim.x;
    for (size_t i = (size_t)blockIdx.x * blockDim.x + threadIdx.x; i < n4; i += stride) {
        float4 v = ((const float4*)in)[i];
        bf162 a, b;
        a.x = __float2bfloat16(v.x); a.y = __float2bfloat16(v.y);
        b.x = __float2bfloat16(v.z); b.y = __float2bfloat16(v.w);
        ((bf162*)out)[i * 2] = a;
        ((bf162*)out)[i * 2 + 1] = b;
    }
}

__global__ void pack3w(const float* __restrict__ Wk, const float* __restrict__ Wq,
                       const float* __restrict__ Wv, bf16* __restrict__ out, int Kd, int Fo) {
    size_t total4 = (size_t)TT * Kd * 3 * Fo / 4;
    size_t stride = (size_t)gridDim.x * blockDim.x;
    for (size_t i = (size_t)blockIdx.x * blockDim.x + threadIdx.x; i < total4; i += stride) {
        size_t idx = i * 4;
        int j = (int)(idx % (size_t)(3 * Fo));
        size_t tk = idx / (size_t)(3 * Fo);
        int m = j / Fo, c = j % Fo;
        const float* W = (m == 0) ? Wk : ((m == 1) ? Wq : Wv);
        float4 v = *(const float4*)(W + tk * Fo + c);
        bf162 a, b;
        a.x = __float2bfloat16(v.x); a.y = __float2bfloat16(v.y);
        b.x = __float2bfloat16(v.z); b.y = __float2bfloat16(v.w);
        bf162* o = (bf162*)(out + idx);
        o[0] = a; o[1] = b;
    }
}

// pack rel weights: BP[mat][st][h][k][idx*D + n] = REL[mat][2*st+idx][h][k][n]
__global__ void packrel(const float* __restrict__ arel, const float* __restrict__ mrel,
                        bf16* __restrict__ BP, int D)
{
    size_t total4 = (size_t)2 * 2 * 8 * D * 2 * D / 4;
    size_t stride = (size_t)gridDim.x * blockDim.x;
    for (size_t i = (size_t)blockIdx.x * blockDim.x + threadIdx.x; i < total4; i += stride) {
        size_t idx = i * 4;
        int twoD = 2 * D;
        int n2 = (int)(idx % (size_t)twoD);
        size_t r = idx / (size_t)twoD;
        int k = (int)(r % D); r /= D;
        int h = (int)(r % 8); r /= 8;
        int st = (int)(r % 2);
        int mat = (int)(r / 2);
        int half = n2 / D, n = n2 % D;
        int e = st * 2 + half;
        const float* R = (mat == 0 ? arel : mrel) + (((size_t)e * 8 + h) * D + k) * D + n;
        float4 v = *(const float4*)R;
        bf162 a, b;
        a.x = __float2bfloat16(v.x); a.y = __float2bfloat16(v.y);
        b.x = __float2bfloat16(v.z); b.y = __float2bfloat16(v.w);
        bf162* o = (bf162*)(BP + idx);
        o[0] = a; o[1] = b;
    }
}

// ---------------- CSR build kernels ----------------
__global__ void zero_int(int* p, int n) {
    int i = blockIdx.x * blockDim.x + threadIdx.x;
    if (i < n) p[i] = 0;
}

__global__ void hist_edges(const int* __restrict__ d0, const int* __restrict__ d1,
                           const int* __restrict__ d2, const int* __restrict__ d3,
                           int* __restrict__ deg4)
{
    int idx = blockIdx.x * blockDim.x + threadIdx.x;
    if (idx >= 4 * EE) return;
    int t = idx / EE, e = idx % EE;
    int dn = (t == 0 ? d0 : (t == 1 ? d1 : (t == 2 ? d2 : d3)))[e];
    atomicAdd(&deg4[t * NN + dn], 1);
}

__global__ void scan_deg(int* __restrict__ deg4, int* __restrict__ rowptr4)
{
    int t = blockIdx.x;
    int* deg = deg4 + t * NN;
    int* rp = rowptr4 + t * (NN + 1);
    __shared__ int sums[256];
    int tid = threadIdx.x;
    const int CH = (NN + 255) / 256;
    int base = tid * CH;
    int s = 0;
    for (int i = 0; i < CH; i++) {
        int idx = base + i;
        if (idx < NN) s += deg[idx];
    }
    sums[tid] = s;
    __syncthreads();
    for (int off = 1; off < 256; off <<= 1) {
        int v = (tid >= off) ? sums[tid - off] : 0;
        __syncthreads();
        if (tid >= off) sums[tid] += v;
        __syncthreads();
    }
    int run = (tid == 0) ? 0 : sums[tid - 1];
    for (int i = 0; i < CH; i++) {
        int idx = base + i;
        if (idx < NN) {
            int d = deg[idx];
            rp[idx] = run;
            deg[idx] = run;
            run += d;
        }
    }
    if (tid == 255) rp[NN] = sums[255];
}

__global__ void scatter_edges(const int* __restrict__ d0, const int* __restrict__ d1,
                              const int* __restrict__ d2, const int* __restrict__ d3,
                              int* __restrict__ cursor4, int* __restrict__ list4)
{
    int idx = blockIdx.x * blockDim.x + threadIdx.x;
    if (idx >= 4 * EE) return;
    int t = idx / EE, e = idx % EE;
    int dn = (t == 0 ? d0 : (t == 1 ? d1 : (t == 2 ? d2 : d3)))[e];
    int pos = atomicAdd(&cursor4[t * NN + dn], 1);
    list4[t * EE + pos] = e;
}

// ---------------- BIG bf16 GEMM: 128x128x32, 4 warps (64x64), 4-stage, 2 CTA/SM ----
// bias: 3-way select (bk|bq|bv) by column block of size Fo; bias value = bp[z*Fo + col%Fo].
#define G2STAGES 4
#define G2SMEM_BYTES (G2STAGES * (128 * 40 + 32 * 136) * 2)

__global__ __launch_bounds__(128, 2)
void gemm_bf2(const bf16* __restrict__ A, const bf16* __restrict__ B,
              const float* __restrict__ bk, const float* __restrict__ bq,
              const float* __restrict__ bv, int Fo,
              bf16* __restrict__ C, int M, int Nn, int K,
              size_t sA, size_t sB, size_t sC)
{
    extern __shared__ char dynsmem[];
    bf16 (*As)[128][40] = (bf16(*)[128][40])dynsmem;
    bf16 (*Bs)[32][136] = (bf16(*)[32][136])(dynsmem + G2STAGES * 128 * 40 * 2);

    int z = blockIdx.z;
    A += (size_t)z * sA;
    B += (size_t)z * sB;
    C += (size_t)z * sC;

    int bm = blockIdx.y * 128, bn = blockIdx.x * 128;
    int tid = threadIdx.x;
    int lane = tid & 31;
    int w = tid >> 5;
    int wm = (w & 1) * 64;
    int wn = (w >> 1) * 64;
    int tg = lane & 3;
    int rowg = lane >> 2;

    float acc[4][8][4];
#pragma unroll
    for (int i = 0; i < 4; i++)
#pragma unroll
        for (int j = 0; j < 8; j++)
#pragma unroll
            for (int r = 0; r < 4; r++) acc[i][j][r] = 0.f;

    const int nk = K / 32;

#define G2LOAD(kt, s)                                                                  \
    do {                                                                               \
        _Pragma("unroll")                                                              \
        for (int p = 0; p < 4; p++) {                                                  \
            int idx = tid + p * 128;                                                   \
            int m = idx >> 2, c = (idx & 3) * 8;                                       \
            int gm = bm + m;                                                           \
            const bf16* sp = A + (size_t)(gm < M ? gm : 0) * K + (kt) + c;             \
            cp16(smem_u32(&As[s][m][c]), sp, gm < M ? 16 : 0);                         \
        }                                                                              \
        _Pragma("unroll")                                                              \
        for (int p = 0; p < 4; p++) {                                                  \
            int idx = tid + p * 128;                                                   \
            int kr = idx >> 4, c = (idx & 15) * 8;                                     \
            const bf16* sp = B + (size_t)((kt) + kr) * Nn + bn + c;                    \
            cp16(smem_u32(&Bs[s][kr][c]), sp, 16);                                     \
        }                                                                              \
    } while (0)

#pragma unroll
    for (int s = 0; s < G2STAGES - 1; s++) {
        if (s < nk) G2LOAD(s * 32, s);
        cp_commit();
    }

    for (int it = 0; it < nk; it++) {
        cp_wait<G2STAGES - 2>();
        __syncthreads();
        int nxt = it + G2STAGES - 1;
        if (nxt < nk) G2LOAD(nxt * 32, nxt % G2STAGES);
        cp_commit();

        int cur = it % G2STAGES;
#pragma unroll
        for (int ks = 0; ks < 2; ks++) {
            int k0 = ks * 16;
            uint32_t af[4][4], bfr[8][2];
#pragma unroll
            for (int mt = 0; mt < 4; mt++) {
                int row = wm + mt * 16 + (lane & 15);
                int coff = k0 + ((lane >> 4) << 3);
                ldsm4(af[mt][0], af[mt][1], af[mt][2], af[mt][3],
                      smem_u32(&As[cur][row][coff]));
            }
#pragma unroll
            for (int ntp = 0; ntp < 4; ntp++) {
                int row = k0 + (lane & 7) + ((lane >> 3) & 1) * 8;
                int col = wn + ntp * 16 + ((lane >> 4) << 3);
                uint32_t r0, r1, r2, r3;
                ldsm4t(r0, r1, r2, r3, smem_u32(&Bs[cur][row][col]));
                bfr[ntp * 2][0] = r0; bfr[ntp * 2][1] = r1;
                bfr[ntp * 2 + 1][0] = r2; bfr[ntp * 2 + 1][1] = r3;
            }
#pragma unroll
            for (int mt = 0; mt < 4; mt++)
#pragma unroll
                for (int nt = 0; nt < 8; nt++)
                    mma_bf16(acc[mt][nt], af[mt], bfr[nt]);
        }
    }
#undef G2LOAD

#pragma unroll
    for (int mt = 0; mt < 4; mt++) {
#pragma unroll
        for (int nt = 0; nt < 8; nt++) {
            int gm0 = bm + wm + mt * 16 + rowg;
            int gn0 = bn + wn + nt * 8 + tg * 2;
            int m = gn0 / Fo, c = gn0 - m * Fo;       // pair never straddles Fo (even cols)
            const float* bp = (m == 0) ? bk : ((m == 1) ? bq : bv);
            float b0 = bp[z * Fo + c], b1 = bp[z * Fo + c + 1];
            if (gm0 < M) {
                bf162 v;
                v.x = __float2bfloat16(acc[mt][nt][0] + b0);
                v.y = __float2bfloat16(acc[mt][nt][1] + b1);
                *(bf162*)(C + (size_t)gm0 * Nn + gn0) = v;
            }
            if (gm0 + 8 < M) {
                bf162 v;
                v.x = __float2bfloat16(acc[mt][nt][2] + b0);
                v.y = __float2bfloat16(acc[mt][nt][3] + b1);
                *(bf162*)(C + (size_t)(gm0 + 8) * Nn + gn0) = v;
            }
        }
    }
}

// ---------------- 128x128 bf16 GEMM (paired rel transforms), 4-stage, 256 thr --------
#define GSTAGES 4
#define GSMEM_BYTES (GSTAGES * (128 * 40 + 32 * 136) * 2)

__global__ __launch_bounds__(256, 2)
void gemm_bf(const bf16* __restrict__ A, const bf16* __restrict__ B,
             const float* __restrict__ bias, bf16* __restrict__ C,
             int M, int Nn, int K, int lda, int ldb, int ldc,
             size_t sA, size_t sA2, size_t sB, size_t sB2,
             size_t sBias, size_t sC, size_t sC2)
{
    extern __shared__ char dynsmem[];
    bf16 (*As)[128][40] = (bf16(*)[128][40])dynsmem;
    bf16 (*Bs)[32][136] = (bf16(*)[32][136])(dynsmem + GSTAGES * 128 * 40 * 2);

    int z = blockIdx.z;
    int zl = z & 7, zh = z >> 3;
    A += (size_t)zl * sA + (size_t)zh * sA2;
    B += (size_t)zl * sB + (size_t)zh * sB2;
    C += (size_t)zl * sC + (size_t)zh * sC2;
    if (bias) bias += (size_t)zl * sBias;

    int bm = blockIdx.y * 128, bn = blockIdx.x * 128;
    int tid = threadIdx.x;
    int lane = tid & 31;
    int w = tid >> 5;
    int wm = (w & 1) * 64;
    int wn = (w >> 1) * 32;
    int tg = lane & 3;
    int rowg = lane >> 2;

    float acc[4][4][4];
#pragma unroll
    for (int i = 0; i < 4; i++)
#pragma unroll
        for (int j = 0; j < 4; j++)
#pragma unroll
            for (int r = 0; r < 4; r++) acc[i][j][r] = 0.f;

    const int nk = K / 32;

#define GLOAD(kt, s)                                                                   \
    do {                                                                               \
        _Pragma("unroll")                                                              \
        for (int p = 0; p < 2; p++) {                                                  \
            int idx = tid + p * 256;                                                   \
            int m = idx >> 2, c = (idx & 3) * 8;                                       \
            int gm = bm + m;                                                           \
            const bf16* sp = A + (size_t)(gm < M ? gm : 0) * lda + (kt) + c;           \
            cp16(smem_u32(&As[s][m][c]), sp, gm < M ? 16 : 0);                         \
        }                                                                              \
        _Pragma("unroll")                                                              \
        for (int p = 0; p < 2; p++) {                                                  \
            int idx = tid + p * 256;                                                   \
            int kr = idx >> 4, c = (idx & 15) * 8;                                     \
            int gn = bn + c;                                                           \
            const bf16* sp = B + (size_t)((kt) + kr) * ldb + (gn < Nn ? gn : 0);       \
            cp16(smem_u32(&Bs[s][kr][c]), sp, gn < Nn ? 16 : 0);                       \
        }                                                                              \
    } while (0)

#pragma unroll
    for (int s = 0; s < GSTAGES - 1; s++) {
        if (s < nk) GLOAD(s * 32, s);
        cp_commit();
    }

    for (int it = 0; it < nk; it++) {
        cp_wait<GSTAGES - 2>();
        __syncthreads();
        int nxt = it + GSTAGES - 1;
        int slot = nxt % GSTAGES;
        if (nxt < nk) GLOAD(nxt * 32, slot);
        cp_commit();

        int cur = it % GSTAGES;
#pragma unroll
        for (int ks = 0; ks < 2; ks++) {
            int k0 = ks * 16;
            uint32_t af[4][4], bfr[4][2];
#pragma unroll
            for (int mt = 0; mt < 4; mt++) {
                int row = wm + mt * 16 + (lane & 15);
                int coff = k0 + ((lane >> 4) << 3);
                ldsm4(af[mt][0], af[mt][1], af[mt][2], af[mt][3],
                      smem_u32(&As[cur][row][coff]));
            }
#pragma unroll
            for (int ntp = 0; ntp < 2; ntp++) {
                int row = k0 + (lane & 7) + ((lane >> 3) & 1) * 8;
                int col = wn + ntp * 16 + ((lane >> 4) << 3);
                uint32_t r0, r1, r2, r3;
                ldsm4t(r0, r1, r2, r3, smem_u32(&Bs[cur][row][col]));
                bfr[ntp * 2][0] = r0; bfr[ntp * 2][1] = r1;
                bfr[ntp * 2 + 1][0] = r2; bfr[ntp * 2 + 1][1] = r3;
            }
#pragma unroll
            for (int mt = 0; mt < 4; mt++)
#pragma unroll
                for (int nt = 0; nt < 4; nt++)
                    mma_bf16(acc[mt][nt], af[mt], bfr[nt]);
        }
    }
#undef GLOAD

#pragma unroll
    for (int mt = 0; mt < 4; mt++) {
#pragma unroll
        for (int nt = 0; nt < 4; nt++) {
            int gm0 = bm + wm + mt * 16 + rowg;
            int gn0 = bn + wn + nt * 8 + tg * 2;
            if (gn0 >= Nn) continue;
            float b0 = 0.f, b1 = 0.f;
            if (bias) { b0 = bias[gn0]; b1 = bias[gn0 + 1]; }
            if (gm0 < M) {
                bf162 v;
                v.x = __float2bfloat16(acc[mt][nt][0] + b0);
                v.y = __float2bfloat16(acc[mt][nt][1] + b1);
                *(bf162*)(C + (size_t)gm0 * ldc + gn0) = v;
            }
            if (gm0 + 8 < M) {
                bf162 v;
                v.x = __float2bfloat16(acc[mt][nt][2] + b0);
                v.y = __float2bfloat16(acc[mt][nt][3] + b1);
                *(bf162*)(C + (size_t)(gm0 + 8) * ldc + gn0) = v;
            }
        }
    }
}

// ---------------- edge logits: ALL 4 edge types in one launch ----------------
__device__ __forceinline__ float dot8(uint4 a, uint4 b) {
    const bf162* pa = (const bf162*)&a;
    const bf162* pb = (const bf162*)&b;
    float s = 0.f;
#pragma unroll
    for (int i = 0; i < 4; i++) {
        float2 fa = __bfloat1622float2(pa[i]);
        float2 fb = __bfloat1622float2(pb[i]);
        s = fmaf(fa.x, fb.x, s);
        s = fmaf(fa.y, fb.y, s);
    }
    return s;
}

// warp per edge, all 8 heads; blockIdx.y = edge type.
// q = kqv[dt] Q section (head stride D); kr = paired KR[st] + idx*D (head stride 2D).
template<int D, int F>
__global__ void edge_logits_all(const bf16* __restrict__ kqv, const bf16* __restrict__ krbase,
                                const int* __restrict__ e0p, const int* __restrict__ e1p,
                                const int* __restrict__ e2p, const int* __restrict__ e3p,
                                const float* __restrict__ prel, float* __restrict__ alpha,
                                float scale)
{
    constexpr int VEC = D / 4;
    constexpr int NV = VEC / 8;
    int et = blockIdx.y;
    int e = (blockIdx.x * blockDim.x + threadIdx.x) >> 5;
    int lane = threadIdx.x & 31;
    if (e >= EE) return;
    const int* ei = (et == 0) ? e0p : ((et == 1) ? e1p : ((et == 2) ? e2p : e3p));
    int dt = et & 1, st = et >> 1;
    int sN = ei[e], dN = ei[EE + e];
    int h = lane >> 2, sub = lane & 3;

    const bf16* q = kqv + (size_t)dt * NN * 3 * F + F;
    const bf16* kr = krbase + (size_t)st * NN * 2 * F + (size_t)(et & 1) * D;
    const uint4* qp = (const uint4*)(q + (size_t)dN * 3 * F + h * D + sub * VEC);
    const uint4* kp = (const uint4*)(kr + (size_t)sN * 2 * F + h * 2 * D + sub * VEC);

    float acc = 0.f;
#pragma unroll
    for (int i = 0; i < NV; i++) acc += dot8(qp[i], kp[i]);
    acc += __shfl_xor_sync(0xFFFFFFFFu, acc, 1);
    acc += __shfl_xor_sync(0xFFFFFFFFu, acc, 2);

    if (sub == 0)
        alpha[((size_t)et * EE + e) * NH + h] = expf(acc * prel[et * NH + h] * scale);
}

// ---------------- CSR gather: warp per (dst node, head), two edge types -------------
template<int D>
__global__ void edge_gather(const bf16* __restrict__ vrA, const bf16* __restrict__ vrB,
                            int ldv, int hsv,
                            const float* __restrict__ alA, const float* __restrict__ alB,
                            const int* __restrict__ srcA, const int* __restrict__ srcB,
                            const int* __restrict__ rpA, const int* __restrict__ listA,
                            const int* __restrict__ rpB, const int* __restrict__ listB,
                            bf16* __restrict__ outp, int F)
{
    constexpr int PL = D / 32;
    int w = (blockIdx.x * blockDim.x + threadIdx.x) >> 5;
    int lane = threadIdx.x & 31;
    if (w >= NN * NH) return;
    int node = w / NH, h = w % NH;
    size_t loff = (size_t)h * hsv + lane * PL;

    float accA[PL], accB[PL];
#pragma unroll
    for (int j = 0; j < PL; j++) { accA[j] = 0.f; accB[j] = 0.f; }
    float sA = 0.f, sB = 0.f;

    int bA = rpA[node], eA = rpA[node + 1];
    for (int i = bA; i < eA; i++) {
        int e = listA[i];
        float ex = alA[(size_t)e * NH + h];
        int s = srcA[e];
        const bf16* vp = vrA + (size_t)s * ldv + loff;
        if (PL == 4) {
            uint2 u = *(const uint2*)vp;
            float2 f0 = __bfloat1622float2(*(const bf162*)&u.x);
            float2 f1 = __bfloat1622float2(*(const bf162*)&u.y);
            accA[0] = fmaf(ex, f0.x, accA[0]);
            accA[1] = fmaf(ex, f0.y, accA[1]);
            accA[2] = fmaf(ex, f1.x, accA[2]);
            accA[3] = fmaf(ex, f1.y, accA[3]);
        } else {
            uint32_t u = *(const uint32_t*)vp;
            float2 f = __bfloat1622float2(*(const bf162*)&u);
            accA[0] = fmaf(ex, f.x, accA[0]);
            accA[1] = fmaf(ex, f.y, accA[1]);
        }
        sA += ex;
    }

    int bB = rpB[node], eB = rpB[node + 1];
    for (int i = bB; i < eB; i++) {
        int e = listB[i];
        float ex = alB[(size_t)e * NH + h];
        int s = srcB[e];
        const bf16* vp = vrB + (size_t)s * ldv + loff;
        if (PL == 4) {
            uint2 u = *(const uint2*)vp;
            float2 f0 = __bfloat1622float2(*(const bf162*)&u.x);
            float2 f1 = __bfloat1622float2(*(const bf162*)&u.y);
            accB[0] = fmaf(ex, f0.x, accB[0]);
            accB[1] = fmaf(ex, f0.y, accB[1]);
            accB[2] = fmaf(ex, f1.x, accB[2]);
            accB[3] = fmaf(ex, f1.y, accB[3]);
        } else {
            uint32_t u = *(const uint32_t*)vp;
            float2 f = __bfloat1622float2(*(const bf162*)&u);
            accB[0] = fmaf(ex, f.x, accB[0]);
            accB[1] = fmaf(ex, f.y, accB[1]);
        }
        sB += ex;
    }

    float invA = 1.f / (sA + 1e-16f);
    float invB = 1.f / (sB + 1e-16f);
    bf16* op = outp + (size_t)node * F + (size_t)h * D + lane * PL;
#pragma unroll
    for (int j = 0; j < PL; j += 2) {
        float x0 = accA[j] * invA + accB[j] * invB;
        float x1 = accA[j + 1] * invA + accB[j + 1] * invB;
        bf162 r;
        r.x = __float2bfloat16(0.5f * x0 * (1.0f + erff(x0 * 0.70710678f)));
        r.y = __float2bfloat16(0.5f * x1 * (1.0f + erff(x1 * 0.70710678f)));
        *(bf162*)(op + j) = r;
    }
}

// ---------------- final linear + row softmax ----------------
__global__ void final_kernel(const bf16* __restrict__ h2, const float* __restrict__ W,
                             const float* __restrict__ b, float* __restrict__ out)
{
    int warp = (blockIdx.x * blockDim.x + threadIdx.x) >> 5;
    int lane = threadIdx.x & 31;
    if (warp >= TT * NN) return;
    const bf16* hp = h2 + (size_t)warp * F2;
    float acc[OUTF];
#pragma unroll
    for (int o = 0; o < OUTF; o++) acc[o] = 0.f;
    for (int f = lane; f < F2; f += 32) {
        float xv = __bfloat162float(hp[f]);
        const float* wp = W + (size_t)f * OUTF;
#pragma unroll
        for (int o = 0; o < OUTF; o++) acc[o] = fmaf(xv, wp[o], acc[o]);
    }
#pragma unroll
    for (int o = 0; o < OUTF; o++) {
#pragma unroll
        for (int off = 16; off; off >>= 1) acc[o] += __shfl_down_sync(0xFFFFFFFFu, acc[o], off);
    }
    if (lane == 0) {
        float l[OUTF];
        float m = -1e30f;
#pragma unroll
        for (int o = 0; o < OUTF; o++) { l[o] = acc[o] + b[o]; m = fmaxf(m, l[o]); }
        float s = 0.f;
#pragma unroll
        for (int o = 0; o < OUTF; o++) { l[o] = expf(l[o] - m); s += l[o]; }
        float inv = 1.f / s;
        float* op = out + (size_t)warp * OUTF;
#pragma unroll
        for (int o = 0; o < OUTF; o++) op[o] = l[o] * inv;
    }
}

// ---------------- host helpers ----------------
static void gemm_big(const bf16* A, const bf16* B, bf16* C, int M, int N, int K,
                     size_t sA, size_t sB, size_t sC,
                     const float* bk, const float* bq, const float* bv, int Fo)
{
    dim3 grid(N / 128, (M + 127) / 128, TT);
    gemm_bf2<<<grid, 128, G2SMEM_BYTES>>>(A, B, bk, bq, bv, Fo, C, M, N, K, sA, sB, sC);
}

// paired rel: one launch per (layer, st): z = mat*8 + h; C = KR[st] (K), +vroff (V)
// B strides: per-head sB = D*2D; per-mat sB2 = 2*8*D*2D (BP layout [mat][st][h][D][2D]).
static void gemm_relp(const bf16* Abase, const bf16* BPst, bf16* Cbase,
                      int D, int F, size_t vroff)
{
    dim3 grid((2 * D + 127) / 128, (NN + 127) / 128, 16);
    gemm_bf<<<grid, 256, GSMEM_BYTES>>>(Abase, BPst, nullptr, Cbase,
        NN, 2 * D, D, 3 * F, 2 * D, 2 * F,
        (size_t)D, (size_t)2 * F,
        (size_t)D * 2 * D, (size_t)2 * 8 * D * 2 * D,   // FIX: mat stride skips both st slots
        0, (size_t)2 * D, vroff);
}

extern "C" void kernel_launch(void* const* d_in, const int* in_sizes, int n_in,
                              void* d_out, int out_size)
{
    (void)in_sizes; (void)n_in; (void)out_size;
    const float* x     = (const float*)d_in[0];
    const int* ei[4]   = {(const int*)d_in[1], (const int*)d_in[2],
                          (const int*)d_in[3], (const int*)d_in[4]};
    const float* Wk1 = (const float*)d_in[5];  const float* bk1 = (const float*)d_in[6];
    const float* Wq1 = (const float*)d_in[7];  const float* bq1 = (const float*)d_in[8];
    const float* Wv1 = (const float*)d_in[9];  const float* bv1 = (const float*)d_in[10];
    const float* Wa1 = (const float*)d_in[11]; const float* ba1 = (const float*)d_in[12];
    const float* arel1 = (const float*)d_in[13];
    const float* mrel1 = (const float*)d_in[14];
    const float* prel1 = (const float*)d_in[15];
    const float* Wk2 = (const float*)d_in[16]; const float* bk2 = (const float*)d_in[17];
    const float* Wq2 = (const float*)d_in[18]; const float* bq2 = (const float*)d_in[19];
    const float* Wv2 = (const float*)d_in[20]; const float* bv2 = (const float*)d_in[21];
    const float* Wa2 = (const float*)d_in[22]; const float* ba2 = (const float*)d_in[23];
    const float* arel2 = (const float*)d_in[24];
    const float* mrel2 = (const float*)d_in[25];
    const float* prel2 = (const float*)d_in[26];
    const float* Wlin = (const float*)d_in[27]; const float* blin = (const float*)d_in[28];
    float* out = (float*)d_out;

    cudaFuncSetAttribute(gemm_bf, cudaFuncAttributeMaxDynamicSharedMemorySize, GSMEM_BYTES);
    cudaFuncSetAttribute(gemm_bf2, cudaFuncAttributeMaxDynamicSharedMemorySize, G2SMEM_BYTES);

    bf16* BB = nullptr;
    float* ALPHA = nullptr;
    int* DEG = nullptr; int* RP = nullptr; int* LST = nullptr;
    cudaGetSymbolAddress((void**)&BB, g_bf);
    cudaGetSymbolAddress((void**)&ALPHA, g_alpha);
    cudaGetSymbolAddress((void**)&DEG, g_deg);
    cudaGetSymbolAddress((void**)&RP, g_rowptr);
    cudaGetSymbolAddress((void**)&LST, g_list);

    bf16* XB = BB + OB_XB;
    bf16* WKQV1 = BB + OB_WKQV1; bf16* WA1B = BB + OB_WA1; bf16* BP1 = BB + OB_BP1;
    bf16* WKQV2 = BB + OB_WKQV2; bf16* WA2B = BB + OB_WA2; bf16* BP2 = BB + OB_BP2;
    bf16* KQV1 = BB + OB_KQV1; bf16* KR1 = BB + OB_KR1;
    bf16* ACT1 = BB + OB_ACT1; bf16* H1 = BB + OB_H1;
    bf16* KQV2 = BB + OB_KQV2; bf16* KR2 = BB + OB_KR2;
    bf16* ACT2 = BB + OB_ACT2; bf16* H2 = BB + OB_H2;
    bf16* VR1 = BB + OB_VR1;   // = KR1 + mat offset
    bf16* VR2 = BB + OB_VR2;

    const int elb = (EE * 32 + 255) / 256;
    const int ggb = (NN * NH * 32 + 255) / 256;
    const int ceb = (4 * EE + 255) / 256;
    const int* dp[4] = {ei[0] + EE, ei[1] + EE, ei[2] + EE, ei[3] + EE};
    const size_t vroff1 = (size_t)OB_VR1 - OB_KR1;
    const size_t vroff2 = (size_t)OB_VR2 - OB_KR2;

    // ---- launches 1-3; #4 = rel GEMM (profiled) ----
    fused_cvt1<<<3072, 256>>>(x, XB, Wk1, Wq1, Wv1, WKQV1);                     // 1
    packrel<<<1024, 256>>>(arel1, mrel1, BP1, D1);                              // 2
    gemm_big(XB, WKQV1, KQV1, NN, 3 * F1, F0,                                   // 3
             (size_t)NN * F0, (size_t)F0 * 3 * F1, (size_t)NN * 3 * F1,
             bk1, bq1, bv1, F1);
    gemm_relp(KQV1, BP1, KR1, D1, F1, vroff1);                                  // 4 (st=0)
    gemm_relp(KQV1 + (size_t)NN * 3 * F1, BP1 + (size_t)8 * D1 * 2 * D1,        // 5 (st=1)
              KR1 + (size_t)NN * 2 * F1, D1, F1, vroff1);

    // CSR build (shared by both layers)
    zero_int<<<(4 * NN + 255) / 256, 256>>>(DEG, 4 * NN);
    hist_edges<<<ceb, 256>>>(dp[0], dp[1], dp[2], dp[3], DEG);
    scan_deg<<<4, 256>>>(DEG, RP);
    scatter_edges<<<ceb, 256>>>(dp[0], dp[1], dp[2], dp[3], DEG, LST);

    // remaining conversions
    packrel<<<256, 256>>>(arel2, mrel2, BP2, D2);
    cvt_bf4<<<512, 256>>>(Wa1, WA1B, (size_t)TT * F1 * F1 / 4);
    pack3w<<<1024, 256>>>(Wk2, Wq2, Wv2, WKQV2, F1, F2);
    cvt_bf4<<<512, 256>>>(Wa2, WA2B, (size_t)TT * F2 * F2 / 4);

    // ---- layer 1 edge phase ----
    {
        float scale = 1.f / sqrtf((float)D1);
        dim3 g(elb, 4);
        edge_logits_all<D1, F1><<<g, 256>>>(KQV1, KR1, ei[0], ei[1], ei[2], ei[3],
                                            prel1, ALPHA, scale);
    }
    // dst0 <- e0 (st0,idx0), e2 (st1,idx0);  dst1 <- e1 (st0,idx1), e3 (st1,idx1)
    edge_gather<D1><<<ggb, 256>>>(VR1, VR1 + (size_t)NN * 2 * F1, 2 * F1, 2 * D1,
        ALPHA, ALPHA + (size_t)2 * EE * NH, ei[0], ei[2],
        RP, LST, RP + 2 * (NN + 1), LST + 2 * EE, ACT1, F1);
    edge_gather<D1><<<ggb, 256>>>(VR1 + D1, VR1 + (size_t)NN * 2 * F1 + D1, 2 * F1, 2 * D1,
        ALPHA + (size_t)1 * EE * NH, ALPHA + (size_t)3 * EE * NH, ei[1], ei[3],
        RP + 1 * (NN + 1), LST + 1 * EE, RP + 3 * (NN + 1), LST + 3 * EE,
        ACT1 + (size_t)NN * F1, F1);

    gemm_big(ACT1, WA1B, H1, NN, F1, F1,
             (size_t)NN * F1, (size_t)F1 * F1, (size_t)NN * F1, ba1, ba1, ba1, F1);

    // ============ LAYER 2 ============
    gemm_big(H1, WKQV2, KQV2, NN, 3 * F2, F1,
             (size_t)NN * F1, (size_t)F1 * 3 * F2, (size_t)NN * 3 * F2, bk2, bq2, bv2, F2);

    gemm_relp(KQV2, BP2, KR2, D2, F2, vroff2);
    gemm_relp(KQV2 + (size_t)NN * 3 * F2, BP2 + (size_t)8 * D2 * 2 * D2,
              KR2 + (size_t)NN * 2 * F2, D2, F2, vroff2);

    {
        float scale = 1.f / sqrtf((float)D2);
        dim3 g(elb, 4);
        edge_logits_all<D2, F2><<<g, 256>>>(KQV2, KR2, ei[0], ei[1], ei[2], ei[3],
                                            prel2, ALPHA, scale);
    }
    edge_gather<D2><<<ggb, 256>>>(VR2, VR2 + (size_t)NN * 2 * F2, 2 * F2, 2 * D2,
        ALPHA, ALPHA + (size_t)2 * EE * NH, ei[0], ei[2],
        RP, LST, RP + 2 * (NN + 1), LST + 2 * EE, ACT2, F2);
    edge_gather<D2><<<ggb, 256>>>(VR2 + D2, VR2 + (size_t)NN * 2 * F2 + D2, 2 * F2, 2 * D2,
        ALPHA + (size_t)1 * EE * NH, ALPHA + (size_t)3 * EE * NH, ei[1], ei[3],
        RP + 1 * (NN + 1), LST + 1 * EE, RP + 3 * (NN + 1), LST + 3 * EE,
        ACT2 + (size_t)NN * F2, F2);

    gemm_big(ACT2, WA2B, H2, NN, F2, F2,
             (size_t)NN * F2, (size_t)F2 * F2, (size_t)NN * F2, ba2, ba2, ba2, F2);

    // ============ final ============
    final_kernel<<<(TT * NN * 32 + 255) / 256, 256>>>(H2, Wlin, blin, out);
}